// round 1
// baseline (speedup 1.0000x reference)
#include <cuda_runtime.h>
#include <cuda_bf16.h>

// Problem constants (match reference)
#define NN 20000
#define EE 320000
#define EP (EE + NN)          // edges + self loops = 340000
#define BB 128
#define HID 64
#define HEADS 4
#define DD 256                // HID*HEADS
#define CAT 576               // HID + 2*DD
#define ENC_H 512
#define DUEL_H 128

// ---------------- scratch (static device memory; no allocs) ----------------
__device__ float g_h512[NN * ENC_H];      // encoder hidden
__device__ float g_h[NN * HID];           // encoder output
__device__ float g_xl[NN * DD];           // source transform (reused conv1/conv2)
__device__ float g_xr[NN * DD];           // target transform
__device__ float g_ex[EP * HEADS];        // exp(score) per edge/head
__device__ float g_h2[NN * DD];           // relu(conv1)
__device__ float g_h3[NN * DD];           // relu(conv2)
__device__ float g_feat[BB * CAT];
__device__ int   g_deg[NN];
__device__ int   g_off[NN + 1];
__device__ int   g_pos[NN];
__device__ int   g_eid[EP];

// ---------------- CSR build ----------------
__global__ void k_zero_deg() {
    int i = blockIdx.x * blockDim.x + threadIdx.x;
    if (i < NN) g_deg[i] = 0;
}

__global__ void k_count(const int* __restrict__ EI) {
    int e = blockIdx.x * blockDim.x + threadIdx.x;
    if (e >= EP) return;
    int dst = (e < EE) ? EI[EE + e] : (e - EE);
    atomicAdd(&g_deg[dst], 1);
}

__global__ void k_scan() {
    // single block, 1024 threads, 20 elements each
    const int CH = (NN + 1023) / 1024;   // 20
    __shared__ int part[1024];
    int t = threadIdx.x;
    int base = t * CH;
    int local[CH];
    int s = 0;
#pragma unroll
    for (int i = 0; i < CH; i++) {
        int idx = base + i;
        int v = (idx < NN) ? g_deg[idx] : 0;
        local[i] = s;
        s += v;
    }
    part[t] = s;
    __syncthreads();
    for (int o = 1; o < 1024; o <<= 1) {
        int v = (t >= o) ? part[t - o] : 0;
        __syncthreads();
        part[t] += v;
        __syncthreads();
    }
    int ex0 = (t == 0) ? 0 : part[t - 1];
#pragma unroll
    for (int i = 0; i < CH; i++) {
        int idx = base + i;
        if (idx < NN) {
            int v = ex0 + local[i];
            g_off[idx] = v;
            g_pos[idx] = v;
        }
    }
    if (t == 1023) g_off[NN] = ex0 + s;
}

__global__ void k_fill(const int* __restrict__ EI) {
    int e = blockIdx.x * blockDim.x + threadIdx.x;
    if (e >= EP) return;
    int dst = (e < EE) ? EI[EE + e] : (e - EE);
    int p = atomicAdd(&g_pos[dst], 1);
    g_eid[p] = e;
}

// ---------------- GEMM: C[M,Nn] = act(A[M,K] @ W[K,Nn] + b) ----------------
// 64x64 tile, BK=16, 256 threads, 4x4 per thread. K%16==0, Nn%64==0 assumed.
template <int ACT>   // 0=none, 1=relu
__global__ void k_gemm(const float* __restrict__ A, const float* __restrict__ W,
                       const float* __restrict__ bias, float* __restrict__ C,
                       int M, int K, int Nn) {
    __shared__ __align__(16) float As[16][64];
    __shared__ __align__(16) float Ws[16][64];
    const int tid = threadIdx.x;
    const int tx = tid & 15;       // col group
    const int ty = tid >> 4;       // row group
    const int rowBase = blockIdx.y * 64;
    const int colBase = blockIdx.x * 64;

    float acc[4][4];
#pragma unroll
    for (int i = 0; i < 4; i++)
#pragma unroll
        for (int j = 0; j < 4; j++) acc[i][j] = 0.f;

    for (int k0 = 0; k0 < K; k0 += 16) {
        // load A tile (transposed into As[k][m])
#pragma unroll
        for (int i = tid; i < 64 * 16; i += 256) {
            int r = i >> 4, c = i & 15;
            int gr = rowBase + r;
            As[c][r] = (gr < M) ? A[(size_t)gr * K + (k0 + c)] : 0.f;
        }
        // load W tile
#pragma unroll
        for (int i = tid; i < 16 * 64; i += 256) {
            int r = i >> 6, c = i & 63;
            Ws[r][c] = W[(size_t)(k0 + r) * Nn + (colBase + c)];
        }
        __syncthreads();
#pragma unroll
        for (int k = 0; k < 16; k++) {
            float4 a4 = *(const float4*)&As[k][ty * 4];
            float4 w4 = *(const float4*)&Ws[k][tx * 4];
            float a[4] = {a4.x, a4.y, a4.z, a4.w};
            float w[4] = {w4.x, w4.y, w4.z, w4.w};
#pragma unroll
            for (int i = 0; i < 4; i++)
#pragma unroll
                for (int j = 0; j < 4; j++) acc[i][j] += a[i] * w[j];
        }
        __syncthreads();
    }

#pragma unroll
    for (int i = 0; i < 4; i++) {
        int row = rowBase + ty * 4 + i;
        if (row >= M) continue;
#pragma unroll
        for (int j = 0; j < 4; j++) {
            int col = colBase + tx * 4 + j;
            float v = acc[i][j] + bias[col];
            if (ACT == 1) v = fmaxf(v, 0.f);
            C[(size_t)row * Nn + col] = v;
        }
    }
}

// ---------------- edge scores: ex[e,h] = exp(att_h . leaky(xl[src]+xr[dst])) ----------------
__global__ void k_score(const int* __restrict__ EI,
                        const float* __restrict__ xl, const float* __restrict__ xr,
                        const float* __restrict__ att) {
    int warp = (blockIdx.x * blockDim.x + threadIdx.x) >> 5;
    int lane = threadIdx.x & 31;
    if (warp >= EP) return;
    int src, dst;
    if (warp < EE) { src = EI[warp]; dst = EI[EE + warp]; }
    else           { src = dst = warp - EE; }

    const float4* xls = (const float4*)(xl + (size_t)src * DD);
    const float4* xrs = (const float4*)(xr + (size_t)dst * DD);
    const float4* at4 = (const float4*)att;   // [HEADS*HID] = 64 float4, head = f>>4

    float s[4] = {0.f, 0.f, 0.f, 0.f};
#pragma unroll
    for (int it = 0; it < 2; it++) {
        int f = lane + it * 32;
        int h = f >> 4;
        float4 a = xls[f];
        float4 b = xrs[f];
        float4 w = at4[f];
        float vx = a.x + b.x; vx = vx > 0.f ? vx : 0.2f * vx;
        float vy = a.y + b.y; vy = vy > 0.f ? vy : 0.2f * vy;
        float vz = a.z + b.z; vz = vz > 0.f ? vz : 0.2f * vz;
        float vw = a.w + b.w; vw = vw > 0.f ? vw : 0.2f * vw;
        s[h] += vx * w.x + vy * w.y + vz * w.z + vw * w.w;
    }
#pragma unroll
    for (int h = 0; h < 4; h++)
#pragma unroll
        for (int o = 16; o; o >>= 1) s[h] += __shfl_xor_sync(0xffffffffu, s[h], o);
    if (lane < 4) g_ex[(size_t)warp * 4 + lane] = expf(s[lane]);
}

// ---------------- aggregate: out[i,:] = relu( (sum_e ex*xl[src]) / denom + bias ) ----------------
__global__ void k_aggregate(const int* __restrict__ EI,
                            const float* __restrict__ xl,
                            const float* __restrict__ bias,
                            float* __restrict__ out) {
    int i = blockIdx.x;
    int t = threadIdx.x;       // 0..255
    int h = t >> 6;
    int s0 = g_off[i], s1 = g_off[i + 1];

    float denom = 0.f;
    for (int p = s0; p < s1; p++) denom += g_ex[(size_t)g_eid[p] * 4 + h];
    denom += 1e-16f;

    float acc = 0.f;
    for (int p = s0; p < s1; p++) {
        int e = g_eid[p];
        int src = (e < EE) ? EI[e] : (e - EE);
        float a = g_ex[(size_t)e * 4 + h];
        acc += a * xl[(size_t)src * DD + t];
    }
    float v = acc / denom + bias[t];
    out[(size_t)i * DD + t] = fmaxf(v, 0.f);
}

// ---------------- gather features ----------------
__global__ void k_feat(const int* __restrict__ idx,
                       const float* __restrict__ h,
                       const float* __restrict__ h2,
                       const float* __restrict__ h3) {
    int b = blockIdx.x;
    int t = threadIdx.x;   // 0..575
    int n = idx[b];
    float v;
    if (t < HID)            v = h[(size_t)n * HID + t];
    else if (t < HID + DD)  v = h2[(size_t)n * DD + (t - HID)];
    else                    v = h3[(size_t)n * DD + (t - HID - DD)];
    g_feat[(size_t)b * CAT + t] = v;
}

// ---------------- dueling head ----------------
__global__ void k_head(const float* __restrict__ qw1, const float* __restrict__ qb1,
                       const float* __restrict__ qw2, const float* __restrict__ qb2,
                       const float* __restrict__ vw1, const float* __restrict__ vb1,
                       const float* __restrict__ vw2, const float* __restrict__ vb2,
                       float* __restrict__ out) {
    __shared__ float f[CAT];
    __shared__ float r0[DUEL_H], r1[DUEL_H], r2[DUEL_H];
    int b = blockIdx.x;
    int t = threadIdx.x;   // 0..127
    for (int i = t; i < CAT; i += DUEL_H) f[i] = g_feat[(size_t)b * CAT + i];
    __syncthreads();

    float q = 0.f, v = 0.f;
#pragma unroll 4
    for (int k = 0; k < CAT; k++) {
        float fv = f[k];
        q += fv * qw1[(size_t)k * DUEL_H + t];
        v += fv * vw1[(size_t)k * DUEL_H + t];
    }
    q = fmaxf(q + qb1[t], 0.f);
    v = fmaxf(v + vb1[t], 0.f);

    r0[t] = q * qw2[t * 2 + 0];
    r1[t] = q * qw2[t * 2 + 1];
    r2[t] = v * vw2[t];
    __syncthreads();
    for (int o = 64; o; o >>= 1) {
        if (t < o) {
            r0[t] += r0[t + o];
            r1[t] += r1[t + o];
            r2[t] += r2[t + o];
        }
        __syncthreads();
    }
    if (t == 0) {
        float q0 = r0[0] + qb2[0];
        float q1 = r1[0] + qb2[1];
        float vv = r2[0] + vb2[0];
        float m = 0.5f * (q0 + q1);
        out[b * 2 + 0] = q0 - m + vv;
        out[b * 2 + 1] = q1 - m + vv;
    }
}

// ---------------- launch ----------------
extern "C" void kernel_launch(void* const* d_in, const int* in_sizes, int n_in,
                              void* d_out, int out_size) {
    const float* x      = (const float*)d_in[0];
    const int*   EI     = (const int*)  d_in[1];
    const int*   idx    = (const int*)  d_in[2];
    const float* enc_w1 = (const float*)d_in[3];
    const float* enc_b1 = (const float*)d_in[4];
    const float* enc_w2 = (const float*)d_in[5];
    const float* enc_b2 = (const float*)d_in[6];
    const float* wl1    = (const float*)d_in[7];
    const float* bl1    = (const float*)d_in[8];
    const float* wr1    = (const float*)d_in[9];
    const float* br1    = (const float*)d_in[10];
    const float* att1   = (const float*)d_in[11];
    const float* bias1  = (const float*)d_in[12];
    const float* wl2    = (const float*)d_in[13];
    const float* bl2    = (const float*)d_in[14];
    const float* wr2    = (const float*)d_in[15];
    const float* br2    = (const float*)d_in[16];
    const float* att2   = (const float*)d_in[17];
    const float* bias2  = (const float*)d_in[18];
    const float* q_w1   = (const float*)d_in[19];
    const float* q_b1   = (const float*)d_in[20];
    const float* q_w2   = (const float*)d_in[21];
    const float* q_b2   = (const float*)d_in[22];
    const float* v_w1   = (const float*)d_in[23];
    const float* v_b1   = (const float*)d_in[24];
    const float* v_w2   = (const float*)d_in[25];
    const float* v_b2   = (const float*)d_in[26];
    float* out = (float*)d_out;

    float *h512, *h, *xl, *xr, *h2, *h3;
    cudaGetSymbolAddress((void**)&h512, g_h512);
    cudaGetSymbolAddress((void**)&h,    g_h);
    cudaGetSymbolAddress((void**)&xl,   g_xl);
    cudaGetSymbolAddress((void**)&xr,   g_xr);
    cudaGetSymbolAddress((void**)&h2,   g_h2);
    cudaGetSymbolAddress((void**)&h3,   g_h3);

    const int MT = (NN + 63) / 64;   // 313 M-tiles

    // CSR build (reused by both conv layers)
    k_zero_deg<<<(NN + 255) / 256, 256>>>();
    k_count<<<(EP + 255) / 256, 256>>>(EI);
    k_scan<<<1, 1024>>>();
    k_fill<<<(EP + 255) / 256, 256>>>(EI);

    // encoder
    k_gemm<1><<<dim3(ENC_H / 64, MT), 256>>>(x,    enc_w1, enc_b1, h512, NN, 64,    ENC_H);
    k_gemm<1><<<dim3(HID / 64,  MT), 256>>>(h512, enc_w2, enc_b2, h,    NN, ENC_H, HID);

    // conv1 transforms
    k_gemm<0><<<dim3(DD / 64, MT), 256>>>(h, wl1, bl1, xl, NN, HID, DD);
    k_gemm<0><<<dim3(DD / 64, MT), 256>>>(h, wr1, br1, xr, NN, HID, DD);
    k_score<<<(EP * 32 + 255) / 256, 256>>>(EI, xl, xr, att1);
    k_aggregate<<<NN, 256>>>(EI, xl, bias1, h2);

    // conv2 transforms
    k_gemm<0><<<dim3(DD / 64, MT), 256>>>(h2, wl2, bl2, xl, NN, DD, DD);
    k_gemm<0><<<dim3(DD / 64, MT), 256>>>(h2, wr2, br2, xr, NN, DD, DD);
    k_score<<<(EP * 32 + 255) / 256, 256>>>(EI, xl, xr, att2);
    k_aggregate<<<NN, 256>>>(EI, xl, bias2, h3);

    // heads
    k_feat<<<BB, CAT>>>(idx, h, h2, h3);
    k_head<<<BB, DUEL_H>>>(q_w1, q_b1, q_w2, q_b2, v_w1, v_b1, v_w2, v_b2, out);
}

// round 2
// speedup vs baseline: 1.4571x; 1.4571x over previous
#include <cuda_runtime.h>
#include <cuda_bf16.h>

// Problem constants (match reference)
#define NN 20000
#define EE 320000
#define EP (EE + NN)          // edges + self loops = 340000
#define BB 128
#define HID 64
#define HEADS 4
#define DD 256                // HID*HEADS
#define CAT 576               // HID + 2*DD
#define ENC_H 512
#define DUEL_H 128

// ---------------- scratch (static device memory; no allocs) ----------------
__device__ float g_h512[NN * ENC_H];      // encoder hidden
__device__ float g_h[NN * HID];           // encoder output
__device__ float g_xl[NN * DD];           // source transform (reused conv1/conv2)
__device__ float g_xr[NN * DD];           // target transform
__device__ float g_h2[NN * DD];           // relu(conv1)
__device__ float g_h3[NN * DD];           // relu(conv2)
__device__ float g_feat[BB * CAT];
__device__ int   g_deg[NN];
__device__ int   g_off[NN + 1];
__device__ int   g_pos[NN];
__device__ int   g_eid[EP];

// ---------------- CSR build ----------------
__global__ void k_zero_deg() {
    int i = blockIdx.x * blockDim.x + threadIdx.x;
    if (i < NN) g_deg[i] = 0;
}

__global__ void k_count(const int* __restrict__ EI) {
    int e = blockIdx.x * blockDim.x + threadIdx.x;
    if (e >= EP) return;
    int dst = (e < EE) ? EI[EE + e] : (e - EE);
    atomicAdd(&g_deg[dst], 1);
}

__global__ void k_scan() {
    const int CH = (NN + 1023) / 1024;   // 20
    __shared__ int part[1024];
    int t = threadIdx.x;
    int base = t * CH;
    int local[CH];
    int s = 0;
#pragma unroll
    for (int i = 0; i < CH; i++) {
        int idx = base + i;
        int v = (idx < NN) ? g_deg[idx] : 0;
        local[i] = s;
        s += v;
    }
    part[t] = s;
    __syncthreads();
    for (int o = 1; o < 1024; o <<= 1) {
        int v = (t >= o) ? part[t - o] : 0;
        __syncthreads();
        part[t] += v;
        __syncthreads();
    }
    int ex0 = (t == 0) ? 0 : part[t - 1];
#pragma unroll
    for (int i = 0; i < CH; i++) {
        int idx = base + i;
        if (idx < NN) {
            int v = ex0 + local[i];
            g_off[idx] = v;
            g_pos[idx] = v;
        }
    }
    if (t == 1023) g_off[NN] = ex0 + s;
}

__global__ void k_fill(const int* __restrict__ EI) {
    int e = blockIdx.x * blockDim.x + threadIdx.x;
    if (e >= EP) return;
    int dst = (e < EE) ? EI[EE + e] : (e - EE);
    int p = atomicAdd(&g_pos[dst], 1);
    g_eid[p] = e;
}

// ---------------- GEMM: C[M,Nn] = act(A[M,K] @ W[K,Nn] + b) ----------------
// 128x64 tile, BK=16, 256 threads, 8x4 per thread. K%16==0, Nn%64==0.
template <int ACT>   // 0=none, 1=relu
__global__ __launch_bounds__(256)
void k_gemm(const float* __restrict__ A, const float* __restrict__ W,
            const float* __restrict__ bias, float* __restrict__ C,
            int M, int K, int Nn) {
    __shared__ __align__(16) float As[16][128];
    __shared__ __align__(16) float Ws[16][64];
    const int tid = threadIdx.x;
    const int tx = tid & 15;       // col group (4 cols)
    const int ty = tid >> 4;       // row group (8 rows)
    const int rowBase = blockIdx.y * 128;
    const int colBase = blockIdx.x * 64;

    float acc[8][4];
#pragma unroll
    for (int i = 0; i < 8; i++)
#pragma unroll
        for (int j = 0; j < 4; j++) acc[i][j] = 0.f;

    for (int k0 = 0; k0 < K; k0 += 16) {
        // load A tile (transposed into As[k][m]): 128x16 = 2048 elems, 8 per thread
#pragma unroll
        for (int i = tid; i < 128 * 16; i += 256) {
            int r = i >> 4, c = i & 15;
            int gr = rowBase + r;
            As[c][r] = (gr < M) ? A[(size_t)gr * K + (k0 + c)] : 0.f;
        }
        // load W tile: 16x64 = 1024 elems, 4 per thread
#pragma unroll
        for (int i = tid; i < 16 * 64; i += 256) {
            int r = i >> 6, c = i & 63;
            Ws[r][c] = W[(size_t)(k0 + r) * Nn + (colBase + c)];
        }
        __syncthreads();
#pragma unroll
        for (int k = 0; k < 16; k++) {
            float4 a0 = *(const float4*)&As[k][ty * 8];
            float4 a1 = *(const float4*)&As[k][ty * 8 + 4];
            float4 w4 = *(const float4*)&Ws[k][tx * 4];
            float a[8] = {a0.x, a0.y, a0.z, a0.w, a1.x, a1.y, a1.z, a1.w};
            float w[4] = {w4.x, w4.y, w4.z, w4.w};
#pragma unroll
            for (int i = 0; i < 8; i++)
#pragma unroll
                for (int j = 0; j < 4; j++) acc[i][j] += a[i] * w[j];
        }
        __syncthreads();
    }

    float b4[4];
#pragma unroll
    for (int j = 0; j < 4; j++) b4[j] = bias[colBase + tx * 4 + j];
#pragma unroll
    for (int i = 0; i < 8; i++) {
        int row = rowBase + ty * 8 + i;
        if (row >= M) continue;
        float4 o;
        float* ov = (float*)&o;
#pragma unroll
        for (int j = 0; j < 4; j++) {
            float v = acc[i][j] + b4[j];
            if (ACT == 1) v = fmaxf(v, 0.f);
            ov[j] = v;
        }
        *(float4*)&C[(size_t)row * Nn + colBase + tx * 4] = o;
    }
}

// ---------------- fused GATv2 layer: score + softmax + aggregate + relu ------
// grid = NN blocks, 128 threads = 4 warps, warp w handles head w.
// out[i, h*64+d] = relu( (sum_e ex_eh * xl[src_e, h*64+d]) / (sum_e ex_eh) + bias )
__global__ __launch_bounds__(128)
void k_gat(const int* __restrict__ EI,
           const float* __restrict__ xl, const float* __restrict__ xr,
           const float* __restrict__ att, const float* __restrict__ bias,
           float* __restrict__ out) {
    const int i = blockIdx.x;
    const int w = threadIdx.x >> 5;       // head
    const int lane = threadIdx.x & 31;
    const int f = w * HID + lane * 2;     // feature index (2 per lane)
    const int s0 = g_off[i], s1 = g_off[i + 1];

    const float2 xrv = *(const float2*)(xr + (size_t)i * DD + f);
    const float2 atv = *(const float2*)(att + f);

    float acc0 = 0.f, acc1 = 0.f, den = 0.f;
    for (int p = s0; p < s1; p++) {
        int e = g_eid[p];
        int src = (e < EE) ? EI[e] : (e - EE);
        float2 xv = *(const float2*)(xl + (size_t)src * DD + f);
        float v0 = xv.x + xrv.x; v0 = v0 > 0.f ? v0 : 0.2f * v0;
        float v1 = xv.y + xrv.y; v1 = v1 > 0.f ? v1 : 0.2f * v1;
        float s = v0 * atv.x + v1 * atv.y;
#pragma unroll
        for (int o = 16; o; o >>= 1) s += __shfl_xor_sync(0xffffffffu, s, o);
        float ex = __expf(s);
        acc0 += ex * xv.x;
        acc1 += ex * xv.y;
        den  += ex;
    }
    float r = 1.f / (den + 1e-16f);
    out[(size_t)i * DD + f]     = fmaxf(acc0 * r + bias[f], 0.f);
    out[(size_t)i * DD + f + 1] = fmaxf(acc1 * r + bias[f + 1], 0.f);
}

// ---------------- gather features ----------------
__global__ void k_feat(const int* __restrict__ idx,
                       const float* __restrict__ h,
                       const float* __restrict__ h2,
                       const float* __restrict__ h3) {
    int b = blockIdx.x;
    int t = threadIdx.x;   // 0..575
    int n = idx[b];
    float v;
    if (t < HID)            v = h[(size_t)n * HID + t];
    else if (t < HID + DD)  v = h2[(size_t)n * DD + (t - HID)];
    else                    v = h3[(size_t)n * DD + (t - HID - DD)];
    g_feat[(size_t)b * CAT + t] = v;
}

// ---------------- dueling head ----------------
__global__ void k_head(const float* __restrict__ qw1, const float* __restrict__ qb1,
                       const float* __restrict__ qw2, const float* __restrict__ qb2,
                       const float* __restrict__ vw1, const float* __restrict__ vb1,
                       const float* __restrict__ vw2, const float* __restrict__ vb2,
                       float* __restrict__ out) {
    __shared__ float f[CAT];
    __shared__ float r0[DUEL_H], r1[DUEL_H], r2[DUEL_H];
    int b = blockIdx.x;
    int t = threadIdx.x;   // 0..127
    for (int i = t; i < CAT; i += DUEL_H) f[i] = g_feat[(size_t)b * CAT + i];
    __syncthreads();

    float q = 0.f, v = 0.f;
#pragma unroll 4
    for (int k = 0; k < CAT; k++) {
        float fv = f[k];
        q += fv * qw1[(size_t)k * DUEL_H + t];
        v += fv * vw1[(size_t)k * DUEL_H + t];
    }
    q = fmaxf(q + qb1[t], 0.f);
    v = fmaxf(v + vb1[t], 0.f);

    r0[t] = q * qw2[t * 2 + 0];
    r1[t] = q * qw2[t * 2 + 1];
    r2[t] = v * vw2[t];
    __syncthreads();
    for (int o = 64; o; o >>= 1) {
        if (t < o) {
            r0[t] += r0[t + o];
            r1[t] += r1[t + o];
            r2[t] += r2[t + o];
        }
        __syncthreads();
    }
    if (t == 0) {
        float q0 = r0[0] + qb2[0];
        float q1 = r1[0] + qb2[1];
        float vv = r2[0] + vb2[0];
        float m = 0.5f * (q0 + q1);
        out[b * 2 + 0] = q0 - m + vv;
        out[b * 2 + 1] = q1 - m + vv;
    }
}

// ---------------- launch ----------------
extern "C" void kernel_launch(void* const* d_in, const int* in_sizes, int n_in,
                              void* d_out, int out_size) {
    const float* x      = (const float*)d_in[0];
    const int*   EI     = (const int*)  d_in[1];
    const int*   idx    = (const int*)  d_in[2];
    const float* enc_w1 = (const float*)d_in[3];
    const float* enc_b1 = (const float*)d_in[4];
    const float* enc_w2 = (const float*)d_in[5];
    const float* enc_b2 = (const float*)d_in[6];
    const float* wl1    = (const float*)d_in[7];
    const float* bl1    = (const float*)d_in[8];
    const float* wr1    = (const float*)d_in[9];
    const float* br1    = (const float*)d_in[10];
    const float* att1   = (const float*)d_in[11];
    const float* bias1  = (const float*)d_in[12];
    const float* wl2    = (const float*)d_in[13];
    const float* bl2    = (const float*)d_in[14];
    const float* wr2    = (const float*)d_in[15];
    const float* br2    = (const float*)d_in[16];
    const float* att2   = (const float*)d_in[17];
    const float* bias2  = (const float*)d_in[18];
    const float* q_w1   = (const float*)d_in[19];
    const float* q_b1   = (const float*)d_in[20];
    const float* q_w2   = (const float*)d_in[21];
    const float* q_b2   = (const float*)d_in[22];
    const float* v_w1   = (const float*)d_in[23];
    const float* v_b1   = (const float*)d_in[24];
    const float* v_w2   = (const float*)d_in[25];
    const float* v_b2   = (const float*)d_in[26];
    float* out = (float*)d_out;

    float *h512, *h, *xl, *xr, *h2, *h3;
    cudaGetSymbolAddress((void**)&h512, g_h512);
    cudaGetSymbolAddress((void**)&h,    g_h);
    cudaGetSymbolAddress((void**)&xl,   g_xl);
    cudaGetSymbolAddress((void**)&xr,   g_xr);
    cudaGetSymbolAddress((void**)&h2,   g_h2);
    cudaGetSymbolAddress((void**)&h3,   g_h3);

    const int MT = (NN + 127) / 128;   // 157 M-tiles

    // CSR build (reused by both conv layers)
    k_zero_deg<<<(NN + 255) / 256, 256>>>();
    k_count<<<(EP + 255) / 256, 256>>>(EI);
    k_scan<<<1, 1024>>>();
    k_fill<<<(EP + 255) / 256, 256>>>(EI);

    // encoder
    k_gemm<1><<<dim3(ENC_H / 64, MT), 256>>>(x,    enc_w1, enc_b1, h512, NN, 64,    ENC_H);
    k_gemm<1><<<dim3(HID / 64,  MT), 256>>>(h512, enc_w2, enc_b2, h,    NN, ENC_H, HID);

    // conv1: transforms + fused GAT
    k_gemm<0><<<dim3(DD / 64, MT), 256>>>(h, wl1, bl1, xl, NN, HID, DD);
    k_gemm<0><<<dim3(DD / 64, MT), 256>>>(h, wr1, br1, xr, NN, HID, DD);
    k_gat<<<NN, 128>>>(EI, xl, xr, att1, bias1, h2);

    // conv2: transforms + fused GAT
    k_gemm<0><<<dim3(DD / 64, MT), 256>>>(h2, wl2, bl2, xl, NN, DD, DD);
    k_gemm<0><<<dim3(DD / 64, MT), 256>>>(h2, wr2, br2, xr, NN, DD, DD);
    k_gat<<<NN, 128>>>(EI, xl, xr, att2, bias2, h3);

    // heads
    k_feat<<<BB, CAT>>>(idx, h, h2, h3);
    k_head<<<BB, DUEL_H>>>(q_w1, q_b1, q_w2, q_b2, v_w1, v_b1, v_w2, v_b2, out);
}

// round 3
// speedup vs baseline: 1.5185x; 1.0421x over previous
#include <cuda_runtime.h>
#include <cuda_bf16.h>

// Problem constants (match reference)
#define NN 20000
#define EE 320000
#define EP (EE + NN)          // edges + self loops = 340000
#define BB 128
#define HID 64
#define HEADS 4
#define DD 256                // HID*HEADS
#define CAT 576               // HID + 2*DD
#define ENC_H 512
#define DUEL_H 128

// ---------------- scratch (static device memory; no allocs) ----------------
__device__ float g_h512[NN * ENC_H];      // encoder hidden
__device__ float g_h[NN * HID];           // encoder output
__device__ float g_xl[NN * DD];           // source transform (reused conv1/conv2)
__device__ float g_xr[NN * DD];           // target transform
__device__ float g_h2[NN * DD];           // relu(conv1)
__device__ float g_h3[NN * DD];           // relu(conv2)
__device__ float g_feat[BB * CAT];
__device__ int   g_deg[NN];
__device__ int   g_off[NN + 1];
__device__ int   g_pos[NN];
__device__ int   g_eid[EP];

// ---------------- packed f32x2 helpers (Blackwell FFMA2 path) --------------
__device__ __forceinline__ void ffma2(unsigned long long& c,
                                      unsigned long long a,
                                      unsigned long long b) {
    asm("fma.rn.f32x2 %0, %1, %2, %0;" : "+l"(c) : "l"(a), "l"(b));
}
__device__ __forceinline__ unsigned long long bcast2(float x) {
    unsigned long long r;
    asm("mov.b64 %0, {%1, %1};" : "=l"(r) : "f"(x));
    return r;
}
__device__ __forceinline__ float2 unpack2(unsigned long long v) {
    float2 u;
    asm("mov.b64 {%0, %1}, %2;" : "=f"(u.x), "=f"(u.y) : "l"(v));
    return u;
}

// ---------------- CSR build ----------------
__global__ void k_zero_deg() {
    int i = blockIdx.x * blockDim.x + threadIdx.x;
    if (i < NN) g_deg[i] = 0;
}

__global__ void k_count(const int* __restrict__ EI) {
    int e = blockIdx.x * blockDim.x + threadIdx.x;
    if (e >= EP) return;
    int dst = (e < EE) ? EI[EE + e] : (e - EE);
    atomicAdd(&g_deg[dst], 1);
}

__global__ void k_scan() {
    const int CH = (NN + 1023) / 1024;   // 20
    __shared__ int part[1024];
    int t = threadIdx.x;
    int base = t * CH;
    int local[CH];
    int s = 0;
#pragma unroll
    for (int i = 0; i < CH; i++) {
        int idx = base + i;
        int v = (idx < NN) ? g_deg[idx] : 0;
        local[i] = s;
        s += v;
    }
    part[t] = s;
    __syncthreads();
    for (int o = 1; o < 1024; o <<= 1) {
        int v = (t >= o) ? part[t - o] : 0;
        __syncthreads();
        part[t] += v;
        __syncthreads();
    }
    int ex0 = (t == 0) ? 0 : part[t - 1];
#pragma unroll
    for (int i = 0; i < CH; i++) {
        int idx = base + i;
        if (idx < NN) {
            int v = ex0 + local[i];
            g_off[idx] = v;
            g_pos[idx] = v;
        }
    }
    if (t == 1023) g_off[NN] = ex0 + s;
}

__global__ void k_fill(const int* __restrict__ EI) {
    int e = blockIdx.x * blockDim.x + threadIdx.x;
    if (e >= EP) return;
    int dst = (e < EE) ? EI[EE + e] : (e - EE);
    int p = atomicAdd(&g_pos[dst], 1);
    g_eid[p] = e;
}

// ---------------- GEMM: C[M,Nn] = act(A[M,K] @ W[K,Nn] + b) ----------------
// 128xBN tile, BK=16, 256 threads, 8x(BN/16) per thread, packed f32x2 FMA.
// K%16==0, Nn%BN==0 assumed.
template <int ACT, int BN>   // ACT: 0=none, 1=relu; BN: 64 or 128
__global__ __launch_bounds__(256)
void k_gemm(const float* __restrict__ A, const float* __restrict__ W,
            const float* __restrict__ bias, float* __restrict__ C,
            int M, int K, int Nn) {
    constexpr int CPT = BN / 16;   // cols per thread (8 or 4)
    constexpr int NP = CPT / 2;    // packed pairs per row (4 or 2)
    __shared__ __align__(16) float As[128][20];   // [m][k], padded rows
    __shared__ __align__(16) float Ws[16][BN];    // [k][n]

    const int tid = threadIdx.x;
    const int tx = tid & 15;
    const int ty = tid >> 4;
    const int rowBase = blockIdx.y * 128;
    const int colBase = blockIdx.x * BN;

    unsigned long long acc[8][NP];
#pragma unroll
    for (int i = 0; i < 8; i++)
#pragma unroll
        for (int p = 0; p < NP; p++) acc[i][p] = 0ull;

    for (int k0 = 0; k0 < K; k0 += 16) {
        // load A tile: 128 rows x 16 k, 2 float4 per thread, row-major w/ pad
#pragma unroll
        for (int it = 0; it < 2; it++) {
            int idx4 = tid + it * 256;          // 0..511
            int r = idx4 >> 2, c4 = idx4 & 3;
            int gr = rowBase + r;
            float4 v = make_float4(0.f, 0.f, 0.f, 0.f);
            if (gr < M) v = *(const float4*)&A[(size_t)gr * K + k0 + c4 * 4];
            *(float4*)&As[r][c4 * 4] = v;
        }
        // load W tile: 16 x BN
#pragma unroll
        for (int it = 0; it < BN / 64; it++) {
            int idx4 = tid + it * 256;          // 0..(16*BN/4)
            int r = idx4 >> (BN == 128 ? 5 : 4);
            int c4 = idx4 & (BN == 128 ? 31 : 15);
            *(float4*)&Ws[r][c4 * 4] = *(const float4*)&W[(size_t)(k0 + r) * Nn + colBase + c4 * 4];
        }
        __syncthreads();
#pragma unroll
        for (int k = 0; k < 16; k++) {
            unsigned long long wp[NP];
            if (BN == 128) {
                ulonglong2 q0 = *(const ulonglong2*)&Ws[k][tx * 8];
                ulonglong2 q1 = *(const ulonglong2*)&Ws[k][tx * 8 + 4];
                wp[0] = q0.x; wp[1] = q0.y; wp[2] = q1.x; wp[3] = q1.y;
            } else {
                ulonglong2 q0 = *(const ulonglong2*)&Ws[k][tx * 4];
                wp[0] = q0.x; wp[1] = q0.y;
            }
#pragma unroll
            for (int i = 0; i < 8; i++) {
                unsigned long long a2 = bcast2(As[ty * 8 + i][k]);
#pragma unroll
                for (int p = 0; p < NP; p++) ffma2(acc[i][p], a2, wp[p]);
            }
        }
        __syncthreads();
    }

    float b[CPT];
#pragma unroll
    for (int j = 0; j < CPT; j++) b[j] = bias[colBase + tx * CPT + j];

#pragma unroll
    for (int i = 0; i < 8; i++) {
        int row = rowBase + ty * 8 + i;
        if (row >= M) continue;
        float o[CPT];
#pragma unroll
        for (int p = 0; p < NP; p++) {
            float2 u = unpack2(acc[i][p]);
            float v0 = u.x + b[p * 2];
            float v1 = u.y + b[p * 2 + 1];
            if (ACT == 1) { v0 = fmaxf(v0, 0.f); v1 = fmaxf(v1, 0.f); }
            o[p * 2] = v0; o[p * 2 + 1] = v1;
        }
#pragma unroll
        for (int q = 0; q < CPT / 4; q++)
            *(float4*)&C[(size_t)row * Nn + colBase + tx * CPT + q * 4] = *(float4*)&o[q * 4];
    }
}

// ---------------- fused GATv2 layer: score + softmax + aggregate + relu ------
__global__ __launch_bounds__(128)
void k_gat(const int* __restrict__ EI,
           const float* __restrict__ xl, const float* __restrict__ xr,
           const float* __restrict__ att, const float* __restrict__ bias,
           float* __restrict__ out) {
    const int i = blockIdx.x;
    const int w = threadIdx.x >> 5;       // head
    const int lane = threadIdx.x & 31;
    const int f = w * HID + lane * 2;     // feature index (2 per lane)
    const int s0 = g_off[i], s1 = g_off[i + 1];

    const float2 xrv = *(const float2*)(xr + (size_t)i * DD + f);
    const float2 atv = *(const float2*)(att + f);

    float acc0 = 0.f, acc1 = 0.f, den = 0.f;
    for (int p = s0; p < s1; p++) {
        int e = g_eid[p];
        int src = (e < EE) ? EI[e] : (e - EE);
        float2 xv = *(const float2*)(xl + (size_t)src * DD + f);
        float v0 = xv.x + xrv.x; v0 = v0 > 0.f ? v0 : 0.2f * v0;
        float v1 = xv.y + xrv.y; v1 = v1 > 0.f ? v1 : 0.2f * v1;
        float s = v0 * atv.x + v1 * atv.y;
#pragma unroll
        for (int o = 16; o; o >>= 1) s += __shfl_xor_sync(0xffffffffu, s, o);
        float ex = __expf(s);
        acc0 += ex * xv.x;
        acc1 += ex * xv.y;
        den  += ex;
    }
    float r = 1.f / (den + 1e-16f);
    out[(size_t)i * DD + f]     = fmaxf(acc0 * r + bias[f], 0.f);
    out[(size_t)i * DD + f + 1] = fmaxf(acc1 * r + bias[f + 1], 0.f);
}

// ---------------- gather features ----------------
__global__ void k_feat(const int* __restrict__ idx,
                       const float* __restrict__ h,
                       const float* __restrict__ h2,
                       const float* __restrict__ h3) {
    int b = blockIdx.x;
    int t = threadIdx.x;   // 0..575
    int n = idx[b];
    float v;
    if (t < HID)            v = h[(size_t)n * HID + t];
    else if (t < HID + DD)  v = h2[(size_t)n * DD + (t - HID)];
    else                    v = h3[(size_t)n * DD + (t - HID - DD)];
    g_feat[(size_t)b * CAT + t] = v;
}

// ---------------- dueling head ----------------
__global__ void k_head(const float* __restrict__ qw1, const float* __restrict__ qb1,
                       const float* __restrict__ qw2, const float* __restrict__ qb2,
                       const float* __restrict__ vw1, const float* __restrict__ vb1,
                       const float* __restrict__ vw2, const float* __restrict__ vb2,
                       float* __restrict__ out) {
    __shared__ float f[CAT];
    __shared__ float r0[DUEL_H], r1[DUEL_H], r2[DUEL_H];
    int b = blockIdx.x;
    int t = threadIdx.x;   // 0..127
    for (int i = t; i < CAT; i += DUEL_H) f[i] = g_feat[(size_t)b * CAT + i];
    __syncthreads();

    float q = 0.f, v = 0.f;
#pragma unroll 4
    for (int k = 0; k < CAT; k++) {
        float fv = f[k];
        q += fv * qw1[(size_t)k * DUEL_H + t];
        v += fv * vw1[(size_t)k * DUEL_H + t];
    }
    q = fmaxf(q + qb1[t], 0.f);
    v = fmaxf(v + vb1[t], 0.f);

    r0[t] = q * qw2[t * 2 + 0];
    r1[t] = q * qw2[t * 2 + 1];
    r2[t] = v * vw2[t];
    __syncthreads();
    for (int o = 64; o; o >>= 1) {
        if (t < o) {
            r0[t] += r0[t + o];
            r1[t] += r1[t + o];
            r2[t] += r2[t + o];
        }
        __syncthreads();
    }
    if (t == 0) {
        float q0 = r0[0] + qb2[0];
        float q1 = r1[0] + qb2[1];
        float vv = r2[0] + vb2[0];
        float m = 0.5f * (q0 + q1);
        out[b * 2 + 0] = q0 - m + vv;
        out[b * 2 + 1] = q1 - m + vv;
    }
}

// ---------------- launch ----------------
extern "C" void kernel_launch(void* const* d_in, const int* in_sizes, int n_in,
                              void* d_out, int out_size) {
    const float* x      = (const float*)d_in[0];
    const int*   EI     = (const int*)  d_in[1];
    const int*   idx    = (const int*)  d_in[2];
    const float* enc_w1 = (const float*)d_in[3];
    const float* enc_b1 = (const float*)d_in[4];
    const float* enc_w2 = (const float*)d_in[5];
    const float* enc_b2 = (const float*)d_in[6];
    const float* wl1    = (const float*)d_in[7];
    const float* bl1    = (const float*)d_in[8];
    const float* wr1    = (const float*)d_in[9];
    const float* br1    = (const float*)d_in[10];
    const float* att1   = (const float*)d_in[11];
    const float* bias1  = (const float*)d_in[12];
    const float* wl2    = (const float*)d_in[13];
    const float* bl2    = (const float*)d_in[14];
    const float* wr2    = (const float*)d_in[15];
    const float* br2    = (const float*)d_in[16];
    const float* att2   = (const float*)d_in[17];
    const float* bias2  = (const float*)d_in[18];
    const float* q_w1   = (const float*)d_in[19];
    const float* q_b1   = (const float*)d_in[20];
    const float* q_w2   = (const float*)d_in[21];
    const float* q_b2   = (const float*)d_in[22];
    const float* v_w1   = (const float*)d_in[23];
    const float* v_b1   = (const float*)d_in[24];
    const float* v_w2   = (const float*)d_in[25];
    const float* v_b2   = (const float*)d_in[26];
    float* out = (float*)d_out;

    float *h512, *h, *xl, *xr, *h2, *h3;
    cudaGetSymbolAddress((void**)&h512, g_h512);
    cudaGetSymbolAddress((void**)&h,    g_h);
    cudaGetSymbolAddress((void**)&xl,   g_xl);
    cudaGetSymbolAddress((void**)&xr,   g_xr);
    cudaGetSymbolAddress((void**)&h2,   g_h2);
    cudaGetSymbolAddress((void**)&h3,   g_h3);

    const int MT = (NN + 127) / 128;   // 157 M-tiles

    // CSR build (reused by both conv layers)
    k_zero_deg<<<(NN + 255) / 256, 256>>>();
    k_count<<<(EP + 255) / 256, 256>>>(EI);
    k_scan<<<1, 1024>>>();
    k_fill<<<(EP + 255) / 256, 256>>>(EI);

    // encoder
    k_gemm<1, 128><<<dim3(ENC_H / 128, MT), 256>>>(x,    enc_w1, enc_b1, h512, NN, 64,    ENC_H);
    k_gemm<1, 64><<<dim3(1, MT), 256>>>(h512, enc_w2, enc_b2, h, NN, ENC_H, HID);

    // conv1: transforms + fused GAT
    k_gemm<0, 128><<<dim3(DD / 128, MT), 256>>>(h, wl1, bl1, xl, NN, HID, DD);
    k_gemm<0, 128><<<dim3(DD / 128, MT), 256>>>(h, wr1, br1, xr, NN, HID, DD);
    k_gat<<<NN, 128>>>(EI, xl, xr, att1, bias1, h2);

    // conv2: transforms + fused GAT
    k_gemm<0, 128><<<dim3(DD / 128, MT), 256>>>(h2, wl2, bl2, xl, NN, DD, DD);
    k_gemm<0, 128><<<dim3(DD / 128, MT), 256>>>(h2, wr2, br2, xr, NN, DD, DD);
    k_gat<<<NN, 128>>>(EI, xl, xr, att2, bias2, h3);

    // heads
    k_feat<<<BB, CAT>>>(idx, h, h2, h3);
    k_head<<<BB, DUEL_H>>>(q_w1, q_b1, q_w2, q_b2, v_w1, v_b1, v_w2, v_b2, out);
}

// round 5
// speedup vs baseline: 2.1891x; 1.4416x over previous
#include <cuda_runtime.h>
#include <cuda_bf16.h>
#include <cstdint>

// Problem constants
#define NN 20000
#define EE 320000
#define EP (EE + NN)          // 340000
#define BB 128
#define HID 64
#define HEADS 4
#define DD 256
#define CAT 576
#define ENC_H 512
#define DUEL_H 128

// ================= scratch (static device memory) ============================
__device__ float g_h[NN * HID];
__device__ float g_xl[NN * DD];
__device__ float g_xr[NN * DD];
__device__ float g_h2[NN * DD];
__device__ float g_h3[NN * DD];
__device__ float g_feat[BB * CAT];
__device__ int   g_deg[NN];
__device__ int   g_off[NN + 1];
__device__ int   g_pos[NN];
__device__ int   g_eid[EP];
// bf16 hi/lo activations
__device__ __nv_bfloat16 g_xh[NN * HID],      g_xlo[NN * HID];
__device__ __nv_bfloat16 g_h512h[NN * ENC_H], g_h512l[NN * ENC_H];
__device__ __nv_bfloat16 g_hh[NN * HID],      g_hl[NN * HID];
__device__ __nv_bfloat16 g_h2h[NN * DD],      g_h2l[NN * DD];
// transposed bf16 hi/lo weights, packed pool  (layout [N][K])
#define WOFF_ENC1 0          // [512][64]
#define WOFF_ENC2 32768      // [64][512]
#define WOFF_WL1  65536      // [256][64]
#define WOFF_WR1  81920
#define WOFF_WL2  98304      // [256][256]
#define WOFF_WR2  163840
#define WPOOL     229376
__device__ __nv_bfloat16 g_wth[WPOOL], g_wtl[WPOOL];

__device__ __forceinline__ void split_bf16(float v, __nv_bfloat16& hi, __nv_bfloat16& lo) {
    hi = __float2bfloat16(v);
    lo = __float2bfloat16(v - __bfloat162float(hi));
}

// bf16 mma.sync (sm_80+ baseline feature; valid on plain sm_103 target)
__device__ __forceinline__ void mma16816(float* c, const uint32_t* a, const uint32_t* b) {
    asm volatile(
        "mma.sync.aligned.m16n8k16.row.col.f32.bf16.bf16.f32 "
        "{%0,%1,%2,%3}, {%4,%5,%6,%7}, {%8,%9}, {%0,%1,%2,%3};"
        : "+f"(c[0]), "+f"(c[1]), "+f"(c[2]), "+f"(c[3])
        : "r"(a[0]), "r"(a[1]), "r"(a[2]), "r"(a[3]), "r"(b[0]), "r"(b[1]));
}

// ================= prep kernels ==============================================
__global__ void k_split_x(const float* __restrict__ x) {
    int i = blockIdx.x * blockDim.x + threadIdx.x;
    if (i >= NN * HID) return;
    split_bf16(x[i], g_xh[i], g_xlo[i]);
}

__global__ void k_wprep(const float* __restrict__ w0, const float* __restrict__ w1,
                        const float* __restrict__ w2, const float* __restrict__ w3,
                        const float* __restrict__ w4, const float* __restrict__ w5) {
    int blk = blockIdx.x;
    const float* src; int K_, N_, dst, start;
    if      (blk < 128) { src = w0; K_ = 64;  N_ = 512; dst = WOFF_ENC1; start = 0;   }
    else if (blk < 256) { src = w1; K_ = 512; N_ = 64;  dst = WOFF_ENC2; start = 128; }
    else if (blk < 320) { src = w2; K_ = 64;  N_ = 256; dst = WOFF_WL1;  start = 256; }
    else if (blk < 384) { src = w3; K_ = 64;  N_ = 256; dst = WOFF_WR1;  start = 320; }
    else if (blk < 640) { src = w4; K_ = 256; N_ = 256; dst = WOFF_WL2;  start = 384; }
    else                { src = w5; K_ = 256; N_ = 256; dst = WOFF_WR2;  start = 640; }
    int e = (blk - start) * 256 + threadIdx.x;
    if (e >= K_ * N_) return;
    int n = e / K_, k = e % K_;
    split_bf16(src[(size_t)k * N_ + n], g_wth[dst + e], g_wtl[dst + e]);
}

// ================= CSR build ================================================
__global__ void k_zero_deg() {
    int i = blockIdx.x * blockDim.x + threadIdx.x;
    if (i < NN) g_deg[i] = 0;
}
__global__ void k_count(const int* __restrict__ EI) {
    int e = blockIdx.x * blockDim.x + threadIdx.x;
    if (e >= EP) return;
    int dst = (e < EE) ? EI[EE + e] : (e - EE);
    atomicAdd(&g_deg[dst], 1);
}
__global__ void k_scan() {
    const int CH = (NN + 1023) / 1024;
    __shared__ int part[1024];
    int t = threadIdx.x, base = t * CH, local[CH], s = 0;
#pragma unroll
    for (int i = 0; i < CH; i++) {
        int idx = base + i;
        int v = (idx < NN) ? g_deg[idx] : 0;
        local[i] = s; s += v;
    }
    part[t] = s;
    __syncthreads();
    for (int o = 1; o < 1024; o <<= 1) {
        int v = (t >= o) ? part[t - o] : 0;
        __syncthreads();
        part[t] += v;
        __syncthreads();
    }
    int ex0 = (t == 0) ? 0 : part[t - 1];
#pragma unroll
    for (int i = 0; i < CH; i++) {
        int idx = base + i;
        if (idx < NN) { int v = ex0 + local[i]; g_off[idx] = v; g_pos[idx] = v; }
    }
    if (t == 1023) g_off[NN] = ex0 + s;
}
__global__ void k_fill(const int* __restrict__ EI) {
    int e = blockIdx.x * blockDim.x + threadIdx.x;
    if (e >= EP) return;
    int dst = (e < EE) ? EI[EE + e] : (e - EE);
    int p = atomicAdd(&g_pos[dst], 1);
    g_eid[p] = e;
}

// ================= HMMA GEMM =================================================
// C[M,Nn] = act(A @ W + b). A bf16 hi/lo [M][K]; W transposed bf16 hi/lo [Nn][K].
// 3-pass split AhWh + AhWl + AlWh, fp32 accum. 256 threads = 8 warps.
// Warp tile 32x64 (2 x 8 of m16n8k16). BK=64. Padded smem stride 72 elems.
#define SSTR 72
template <int BM, int BN, int ACT, int WF32, int WB16>
__global__ __launch_bounds__(256)
void k_mma(const __nv_bfloat16* __restrict__ Ah, const __nv_bfloat16* __restrict__ Al,
           const __nv_bfloat16* __restrict__ Bh, const __nv_bfloat16* __restrict__ Bl,
           const float* __restrict__ bias, float* __restrict__ Cf,
           __nv_bfloat16* __restrict__ Ch, __nv_bfloat16* __restrict__ Cl,
           int M, int K, int Nn) {
    extern __shared__ __nv_bfloat16 smem[];
    __nv_bfloat16* sAh = smem;
    __nv_bfloat16* sAl = sAh + BM * SSTR;
    __nv_bfloat16* sBh = sAl + BM * SSTR;
    __nv_bfloat16* sBl = sBh + BN * SSTR;

    const int tid = threadIdx.x;
    const int warp = tid >> 5;
    const int lane = tid & 31;
    const int gid = lane >> 2;        // group id (0..7)
    const int tid4 = lane & 3;        // thread in group
    constexpr int WCOLS = BN / 64;
    const int wR = warp / WCOLS;      // warp row (m)
    const int wC = warp % WCOLS;      // warp col (n)
    const int rowBase = blockIdx.y * BM;
    const int colBase = blockIdx.x * BN;

    float acc[2][8][4];
#pragma unroll
    for (int i = 0; i < 2; i++)
#pragma unroll
        for (int j = 0; j < 8; j++)
#pragma unroll
            for (int q = 0; q < 4; q++) acc[i][j][q] = 0.f;

    for (int k0 = 0; k0 < K; k0 += 64) {
        __syncthreads();
        // load A hi/lo tiles: BM rows x 64 bf16 (8 x uint4 per row)
#pragma unroll
        for (int v = tid; v < BM * 8; v += 256) {
            int r = v >> 3, c8 = v & 7;
            int gr = rowBase + r;
            uint4 vh = make_uint4(0, 0, 0, 0), vl = make_uint4(0, 0, 0, 0);
            if (gr < M) {
                size_t gi = (size_t)gr * K + k0 + c8 * 8;
                vh = *(const uint4*)&Ah[gi];
                vl = *(const uint4*)&Al[gi];
            }
            *(uint4*)&sAh[r * SSTR + c8 * 8] = vh;
            *(uint4*)&sAl[r * SSTR + c8 * 8] = vl;
        }
        // load B hi/lo tiles: BN rows x 64 bf16
#pragma unroll
        for (int v = tid; v < BN * 8; v += 256) {
            int r = v >> 3, c8 = v & 7;
            size_t gi = (size_t)(colBase + r) * K + k0 + c8 * 8;
            *(uint4*)&sBh[r * SSTR + c8 * 8] = *(const uint4*)&Bh[gi];
            *(uint4*)&sBl[r * SSTR + c8 * 8] = *(const uint4*)&Bl[gi];
        }
        __syncthreads();

#pragma unroll
        for (int ks = 0; ks < 4; ks++) {
            const int kb = ks * 16 + tid4 * 2;
            uint32_t ah[2][4], al[2][4];
#pragma unroll
            for (int mf = 0; mf < 2; mf++) {
                int r0 = wR * 32 + mf * 16 + gid;
                ah[mf][0] = *(const uint32_t*)&sAh[r0 * SSTR + kb];
                ah[mf][1] = *(const uint32_t*)&sAh[(r0 + 8) * SSTR + kb];
                ah[mf][2] = *(const uint32_t*)&sAh[r0 * SSTR + kb + 8];
                ah[mf][3] = *(const uint32_t*)&sAh[(r0 + 8) * SSTR + kb + 8];
                al[mf][0] = *(const uint32_t*)&sAl[r0 * SSTR + kb];
                al[mf][1] = *(const uint32_t*)&sAl[(r0 + 8) * SSTR + kb];
                al[mf][2] = *(const uint32_t*)&sAl[r0 * SSTR + kb + 8];
                al[mf][3] = *(const uint32_t*)&sAl[(r0 + 8) * SSTR + kb + 8];
            }
#pragma unroll
            for (int nf = 0; nf < 8; nf++) {
                int n = wC * 64 + nf * 8 + gid;
                uint32_t bh[2], bl[2];
                bh[0] = *(const uint32_t*)&sBh[n * SSTR + kb];
                bh[1] = *(const uint32_t*)&sBh[n * SSTR + kb + 8];
                bl[0] = *(const uint32_t*)&sBl[n * SSTR + kb];
                bl[1] = *(const uint32_t*)&sBl[n * SSTR + kb + 8];
#pragma unroll
                for (int mf = 0; mf < 2; mf++) {
                    mma16816(acc[mf][nf], ah[mf], bh);
                    mma16816(acc[mf][nf], ah[mf], bl);
                    mma16816(acc[mf][nf], al[mf], bh);
                }
            }
        }
    }

    // epilogue: bias + act (+ bf16 split), straight from fragments
#pragma unroll
    for (int nf = 0; nf < 8; nf++) {
        int col = colBase + wC * 64 + nf * 8 + tid4 * 2;
        float b0 = bias[col], b1 = bias[col + 1];
#pragma unroll
        for (int mf = 0; mf < 2; mf++) {
#pragma unroll
            for (int half = 0; half < 2; half++) {
                int row = rowBase + wR * 32 + mf * 16 + gid + half * 8;
                if (row >= M) continue;
                float v0 = acc[mf][nf][half * 2] + b0;
                float v1 = acc[mf][nf][half * 2 + 1] + b1;
                if (ACT == 1) { v0 = fmaxf(v0, 0.f); v1 = fmaxf(v1, 0.f); }
                size_t oi = (size_t)row * Nn + col;
                if (WF32) *(float2*)&Cf[oi] = make_float2(v0, v1);
                if (WB16) {
                    __nv_bfloat162 hh2, ll2;
                    split_bf16(v0, hh2.x, ll2.x);
                    split_bf16(v1, hh2.y, ll2.y);
                    *(__nv_bfloat162*)&Ch[oi] = hh2;
                    *(__nv_bfloat162*)&Cl[oi] = ll2;
                }
            }
        }
    }
}

// ================= fused GATv2 layer =========================================
template <bool WB16>
__global__ __launch_bounds__(128)
void k_gat(const int* __restrict__ EI,
           const float* __restrict__ xl, const float* __restrict__ xr,
           const float* __restrict__ att, const float* __restrict__ bias,
           float* __restrict__ out, __nv_bfloat16* outH, __nv_bfloat16* outL) {
    const int i = blockIdx.x;
    const int w = threadIdx.x >> 5;
    const int lane = threadIdx.x & 31;
    const int f = w * HID + lane * 2;
    const int s0 = g_off[i], s1 = g_off[i + 1];

    const float2 xrv = *(const float2*)(xr + (size_t)i * DD + f);
    const float2 atv = *(const float2*)(att + f);

    float acc0 = 0.f, acc1 = 0.f, den = 0.f;
    for (int p = s0; p < s1; p++) {
        int e = g_eid[p];
        int src = (e < EE) ? EI[e] : (e - EE);
        float2 xv = *(const float2*)(xl + (size_t)src * DD + f);
        float v0 = xv.x + xrv.x; v0 = v0 > 0.f ? v0 : 0.2f * v0;
        float v1 = xv.y + xrv.y; v1 = v1 > 0.f ? v1 : 0.2f * v1;
        float s = v0 * atv.x + v1 * atv.y;
#pragma unroll
        for (int o = 16; o; o >>= 1) s += __shfl_xor_sync(0xffffffffu, s, o);
        float ex = __expf(s);
        acc0 += ex * xv.x; acc1 += ex * xv.y; den += ex;
    }
    float rr = 1.f / (den + 1e-16f);
    float o0 = fmaxf(acc0 * rr + bias[f], 0.f);
    float o1 = fmaxf(acc1 * rr + bias[f + 1], 0.f);
    size_t oi = (size_t)i * DD + f;
    out[oi] = o0; out[oi + 1] = o1;
    if (WB16) {
        __nv_bfloat162 h, l;
        split_bf16(o0, h.x, l.x); split_bf16(o1, h.y, l.y);
        *(__nv_bfloat162*)&outH[oi] = h;
        *(__nv_bfloat162*)&outL[oi] = l;
    }
}

// ================= gather + dueling head =====================================
__global__ void k_feat(const int* __restrict__ idx,
                       const float* __restrict__ h,
                       const float* __restrict__ h2,
                       const float* __restrict__ h3) {
    int b = blockIdx.x, t = threadIdx.x;
    int n = idx[b];
    float v;
    if (t < HID)            v = h[(size_t)n * HID + t];
    else if (t < HID + DD)  v = h2[(size_t)n * DD + (t - HID)];
    else                    v = h3[(size_t)n * DD + (t - HID - DD)];
    g_feat[(size_t)b * CAT + t] = v;
}

__global__ void k_head(const float* __restrict__ qw1, const float* __restrict__ qb1,
                       const float* __restrict__ qw2, const float* __restrict__ qb2,
                       const float* __restrict__ vw1, const float* __restrict__ vb1,
                       const float* __restrict__ vw2, const float* __restrict__ vb2,
                       float* __restrict__ out) {
    __shared__ float f[CAT];
    __shared__ float r0[DUEL_H], r1[DUEL_H], r2[DUEL_H];
    int b = blockIdx.x, t = threadIdx.x;
    for (int i = t; i < CAT; i += DUEL_H) f[i] = g_feat[(size_t)b * CAT + i];
    __syncthreads();
    float q = 0.f, v = 0.f;
#pragma unroll 4
    for (int k = 0; k < CAT; k++) {
        float fv = f[k];
        q += fv * qw1[(size_t)k * DUEL_H + t];
        v += fv * vw1[(size_t)k * DUEL_H + t];
    }
    q = fmaxf(q + qb1[t], 0.f);
    v = fmaxf(v + vb1[t], 0.f);
    r0[t] = q * qw2[t * 2 + 0];
    r1[t] = q * qw2[t * 2 + 1];
    r2[t] = v * vw2[t];
    __syncthreads();
    for (int o = 64; o; o >>= 1) {
        if (t < o) { r0[t] += r0[t + o]; r1[t] += r1[t + o]; r2[t] += r2[t + o]; }
        __syncthreads();
    }
    if (t == 0) {
        float q0 = r0[0] + qb2[0], q1 = r1[0] + qb2[1], vv = r2[0] + vb2[0];
        float m = 0.5f * (q0 + q1);
        out[b * 2 + 0] = q0 - m + vv;
        out[b * 2 + 1] = q1 - m + vv;
    }
}

// ================= launch ====================================================
extern "C" void kernel_launch(void* const* d_in, const int* in_sizes, int n_in,
                              void* d_out, int out_size) {
    const float* x      = (const float*)d_in[0];
    const int*   EI     = (const int*)  d_in[1];
    const int*   idx    = (const int*)  d_in[2];
    const float* enc_w1 = (const float*)d_in[3];
    const float* enc_b1 = (const float*)d_in[4];
    const float* enc_w2 = (const float*)d_in[5];
    const float* enc_b2 = (const float*)d_in[6];
    const float* wl1    = (const float*)d_in[7];
    const float* bl1    = (const float*)d_in[8];
    const float* wr1    = (const float*)d_in[9];
    const float* br1    = (const float*)d_in[10];
    const float* att1   = (const float*)d_in[11];
    const float* bias1  = (const float*)d_in[12];
    const float* wl2    = (const float*)d_in[13];
    const float* bl2    = (const float*)d_in[14];
    const float* wr2    = (const float*)d_in[15];
    const float* br2    = (const float*)d_in[16];
    const float* att2   = (const float*)d_in[17];
    const float* bias2  = (const float*)d_in[18];
    const float* q_w1   = (const float*)d_in[19];
    const float* q_b1   = (const float*)d_in[20];
    const float* q_w2   = (const float*)d_in[21];
    const float* q_b2   = (const float*)d_in[22];
    const float* v_w1   = (const float*)d_in[23];
    const float* v_b1   = (const float*)d_in[24];
    const float* v_w2   = (const float*)d_in[25];
    const float* v_b2   = (const float*)d_in[26];
    float* out = (float*)d_out;

    float *h, *xl, *xr, *h2, *h3;
    __nv_bfloat16 *xh, *xlo, *h512h, *h512l, *hh, *hl, *h2h, *h2l, *wth, *wtl;
    cudaGetSymbolAddress((void**)&h,    g_h);
    cudaGetSymbolAddress((void**)&xl,   g_xl);
    cudaGetSymbolAddress((void**)&xr,   g_xr);
    cudaGetSymbolAddress((void**)&h2,   g_h2);
    cudaGetSymbolAddress((void**)&h3,   g_h3);
    cudaGetSymbolAddress((void**)&xh,   g_xh);
    cudaGetSymbolAddress((void**)&xlo,  g_xlo);
    cudaGetSymbolAddress((void**)&h512h, g_h512h);
    cudaGetSymbolAddress((void**)&h512l, g_h512l);
    cudaGetSymbolAddress((void**)&hh,   g_hh);
    cudaGetSymbolAddress((void**)&hl,   g_hl);
    cudaGetSymbolAddress((void**)&h2h,  g_h2h);
    cudaGetSymbolAddress((void**)&h2l,  g_h2l);
    cudaGetSymbolAddress((void**)&wth,  g_wth);
    cudaGetSymbolAddress((void**)&wtl,  g_wtl);

    const int SM_128 = (2 * 128 + 2 * 128) * SSTR * 2;   // 73,728 B
    const int SM_256 = (2 * 256 + 2 * 64) * SSTR * 2;    // 92,160 B
    cudaFuncSetAttribute((const void*)k_mma<128, 128, 1, 0, 1>, cudaFuncAttributeMaxDynamicSharedMemorySize, SM_128);
    cudaFuncSetAttribute((const void*)k_mma<256, 64, 1, 1, 1>,  cudaFuncAttributeMaxDynamicSharedMemorySize, SM_256);
    cudaFuncSetAttribute((const void*)k_mma<128, 128, 0, 1, 0>, cudaFuncAttributeMaxDynamicSharedMemorySize, SM_128);

    const int MT128 = (NN + 127) / 128;   // 157
    const int MT256 = (NN + 255) / 256;   // 79

    // prep
    k_split_x<<<(NN * HID + 255) / 256, 256>>>(x);
    k_wprep<<<896, 256>>>(enc_w1, enc_w2, wl1, wr1, wl2, wr2);
    k_zero_deg<<<(NN + 255) / 256, 256>>>();

    // enc1: [NN,64] @ [64,512] -> h512 (bf16 hi/lo), relu
    k_mma<128, 128, 1, 0, 1><<<dim3(ENC_H / 128, MT128), 256, SM_128>>>(
        xh, xlo, wth + WOFF_ENC1, wtl + WOFF_ENC1, enc_b1, nullptr, h512h, h512l, NN, 64, ENC_H);
    k_count<<<(EP + 255) / 256, 256>>>(EI);
    // enc2: [NN,512] @ [512,64] -> h (f32 + bf16 hi/lo), relu
    k_mma<256, 64, 1, 1, 1><<<dim3(1, MT256), 256, SM_256>>>(
        h512h, h512l, wth + WOFF_ENC2, wtl + WOFF_ENC2, enc_b2, h, hh, hl, NN, ENC_H, HID);
    k_scan<<<1, 1024>>>();
    k_fill<<<(EP + 255) / 256, 256>>>(EI);

    // conv1 transforms (f32 out only)
    k_mma<128, 128, 0, 1, 0><<<dim3(DD / 128, MT128), 256, SM_128>>>(
        hh, hl, wth + WOFF_WL1, wtl + WOFF_WL1, bl1, xl, nullptr, nullptr, NN, HID, DD);
    k_mma<128, 128, 0, 1, 0><<<dim3(DD / 128, MT128), 256, SM_128>>>(
        hh, hl, wth + WOFF_WR1, wtl + WOFF_WR1, br1, xr, nullptr, nullptr, NN, HID, DD);
    k_gat<true><<<NN, 128>>>(EI, xl, xr, att1, bias1, h2, h2h, h2l);

    // conv2 transforms
    k_mma<128, 128, 0, 1, 0><<<dim3(DD / 128, MT128), 256, SM_128>>>(
        h2h, h2l, wth + WOFF_WL2, wtl + WOFF_WL2, bl2, xl, nullptr, nullptr, NN, DD, DD);
    k_mma<128, 128, 0, 1, 0><<<dim3(DD / 128, MT128), 256, SM_128>>>(
        h2h, h2l, wth + WOFF_WR2, wtl + WOFF_WR2, br2, xr, nullptr, nullptr, NN, DD, DD);
    k_gat<false><<<NN, 128>>>(EI, xl, xr, att2, bias2, h3, nullptr, nullptr);

    // heads
    k_feat<<<BB, CAT>>>(idx, h, h2, h3);
    k_head<<<BB, DUEL_H>>>(q_w1, q_b1, q_w2, q_b2, v_w1, v_b1, v_w2, v_b2, out);
}

// round 6
// speedup vs baseline: 2.3925x; 1.0929x over previous
#include <cuda_runtime.h>
#include <cuda_bf16.h>
#include <cstdint>

// Problem constants
#define NN 20000
#define EE 320000
#define EP (EE + NN)          // 340000
#define BB 128
#define HID 64
#define HEADS 4
#define DD 256
#define CAT 576
#define ENC_H 512
#define DUEL_H 128

// ================= scratch (static device memory) ============================
__device__ float g_h[NN * HID];
__device__ float g_xlr[NN * 512];     // [xl | xr] per row
__device__ float g_h2[NN * DD];
__device__ float g_h3[NN * DD];
__device__ float g_feat[BB * CAT];
__device__ float g_b1[512], g_b2[512];  // pooled conv biases [bl | br]
__device__ int   g_deg[NN];
__device__ int   g_off[NN + 1];
__device__ int   g_pos[NN];
__device__ int   g_eid[EP];
// bf16 hi/lo activations
__device__ __nv_bfloat16 g_xh[NN * HID],      g_xlo[NN * HID];
__device__ __nv_bfloat16 g_h512h[NN * ENC_H], g_h512l[NN * ENC_H];
__device__ __nv_bfloat16 g_hh[NN * HID],      g_hl[NN * HID];
__device__ __nv_bfloat16 g_h2h[NN * DD],      g_h2l[NN * DD];
// transposed bf16 hi/lo weights, packed pool  (layout [N][K]); WL/WR pairs contiguous
#define WOFF_ENC1 0          // [512][64]
#define WOFF_ENC2 32768      // [64][512]
#define WOFF_W1   65536      // [512][64]  (wl1 || wr1)
#define WOFF_W2   98304      // [512][256] (wl2 || wr2)
#define WPOOL     229376
__device__ __nv_bfloat16 g_wth[WPOOL], g_wtl[WPOOL];

__device__ __forceinline__ void split_bf16(float v, __nv_bfloat16& hi, __nv_bfloat16& lo) {
    hi = __float2bfloat16(v);
    lo = __float2bfloat16(v - __bfloat162float(hi));
}

__device__ __forceinline__ uint32_t smem_u32(const void* p) {
    uint32_t a;
    asm("{ .reg .u64 t; cvta.to.shared.u64 t, %1; cvt.u32.u64 %0, t; }" : "=r"(a) : "l"(p));
    return a;
}
__device__ __forceinline__ void cp16(uint32_t d, const void* s, int sz) {
    asm volatile("cp.async.cg.shared.global [%0], [%1], 16, %2;" :: "r"(d), "l"(s), "r"(sz));
}
#define CP_COMMIT() asm volatile("cp.async.commit_group;" ::: "memory")
#define CP_WAIT(n)  asm volatile("cp.async.wait_group %0;" :: "n"(n) : "memory")

// bf16 mma.sync (sm_80+ baseline; valid on plain sm_103 target)
__device__ __forceinline__ void mma16816(float* c, const uint32_t* a, const uint32_t* b) {
    asm volatile(
        "mma.sync.aligned.m16n8k16.row.col.f32.bf16.bf16.f32 "
        "{%0,%1,%2,%3}, {%4,%5,%6,%7}, {%8,%9}, {%0,%1,%2,%3};"
        : "+f"(c[0]), "+f"(c[1]), "+f"(c[2]), "+f"(c[3])
        : "r"(a[0]), "r"(a[1]), "r"(a[2]), "r"(a[3]), "r"(b[0]), "r"(b[1]));
}

// ================= prep kernels ==============================================
__global__ void k_split_x(const float* __restrict__ x) {
    int i = blockIdx.x * blockDim.x + threadIdx.x;
    if (i >= NN * HID) return;
    split_bf16(x[i], g_xh[i], g_xlo[i]);
}

__global__ void k_wprep(const float* __restrict__ w0, const float* __restrict__ w1,
                        const float* __restrict__ w2, const float* __restrict__ w3,
                        const float* __restrict__ w4, const float* __restrict__ w5) {
    int blk = blockIdx.x;
    const float* src; int K_, N_, dst, start;
    if      (blk < 128) { src = w0; K_ = 64;  N_ = 512; dst = WOFF_ENC1;        start = 0;   }
    else if (blk < 256) { src = w1; K_ = 512; N_ = 64;  dst = WOFF_ENC2;        start = 128; }
    else if (blk < 320) { src = w2; K_ = 64;  N_ = 256; dst = WOFF_W1;          start = 256; }
    else if (blk < 384) { src = w3; K_ = 64;  N_ = 256; dst = WOFF_W1 + 16384;  start = 320; }
    else if (blk < 640) { src = w4; K_ = 256; N_ = 256; dst = WOFF_W2;          start = 384; }
    else                { src = w5; K_ = 256; N_ = 256; dst = WOFF_W2 + 65536;  start = 640; }
    int e = (blk - start) * 256 + threadIdx.x;
    if (e >= K_ * N_) return;
    int n = e / K_, k = e % K_;
    split_bf16(src[(size_t)k * N_ + n], g_wth[dst + e], g_wtl[dst + e]);
}

__global__ void k_bprep(const float* __restrict__ bl1, const float* __restrict__ br1,
                        const float* __restrict__ bl2, const float* __restrict__ br2) {
    int t = blockIdx.x * blockDim.x + threadIdx.x;
    if (t >= 1024) return;
    if (t < 256)       g_b1[t] = bl1[t];
    else if (t < 512)  g_b1[t] = br1[t - 256];
    else if (t < 768)  g_b2[t - 512] = bl2[t - 512];
    else               g_b2[t - 512] = br2[t - 768];
}

// ================= CSR build ================================================
__global__ void k_zero_deg() {
    int i = blockIdx.x * blockDim.x + threadIdx.x;
    if (i < NN) g_deg[i] = 0;
}
__global__ void k_count(const int* __restrict__ EI) {
    int e = blockIdx.x * blockDim.x + threadIdx.x;
    if (e >= EP) return;
    int dst = (e < EE) ? EI[EE + e] : (e - EE);
    atomicAdd(&g_deg[dst], 1);
}
__global__ void k_scan() {
    const int CH = (NN + 1023) / 1024;
    __shared__ int part[1024];
    int t = threadIdx.x, base = t * CH, local[CH], s = 0;
#pragma unroll
    for (int i = 0; i < CH; i++) {
        int idx = base + i;
        int v = (idx < NN) ? g_deg[idx] : 0;
        local[i] = s; s += v;
    }
    part[t] = s;
    __syncthreads();
    for (int o = 1; o < 1024; o <<= 1) {
        int v = (t >= o) ? part[t - o] : 0;
        __syncthreads();
        part[t] += v;
        __syncthreads();
    }
    int ex0 = (t == 0) ? 0 : part[t - 1];
#pragma unroll
    for (int i = 0; i < CH; i++) {
        int idx = base + i;
        if (idx < NN) { int v = ex0 + local[i]; g_off[idx] = v; g_pos[idx] = v; }
    }
    if (t == 1023) g_off[NN] = ex0 + s;
}
__global__ void k_fill(const int* __restrict__ EI) {
    int e = blockIdx.x * blockDim.x + threadIdx.x;
    if (e >= EP) return;
    int dst = (e < EE) ? EI[EE + e] : (e - EE);
    int p = atomicAdd(&g_pos[dst], 1);
    g_eid[p] = e;
}

// ================= HMMA GEMM (cp.async 2-stage pipeline) =====================
// C[M,Nn] = act(A @ W + b). A bf16 hi/lo [M][K]; W transposed bf16 hi/lo [Nn][K].
// 3-pass split AhWh + AhWl + AlWh, fp32 accum. 256 threads = 8 warps.
// Warp tile 32x64, BK=32, STR=40 elems (conflict-free frag loads).
#define STR 40
template <int BN, int ACT, int WF32, int WB16>
__global__ __launch_bounds__(256, 2)
void k_mma(const __nv_bfloat16* __restrict__ Ah, const __nv_bfloat16* __restrict__ Al,
           const __nv_bfloat16* __restrict__ Bh, const __nv_bfloat16* __restrict__ Bl,
           const float* __restrict__ bias, float* __restrict__ Cf,
           __nv_bfloat16* __restrict__ Ch, __nv_bfloat16* __restrict__ Cl,
           int M, int K, int Nn) {
    constexpr int BM = (BN == 64) ? 256 : 128;
    constexpr int WCOLS = BN / 64;
    constexpr int STAGE = (2 * BM + 2 * BN) * STR;
    extern __shared__ __nv_bfloat16 smem[];

    const int tid = threadIdx.x;
    const int warp = tid >> 5;
    const int lane = tid & 31;
    const int gid = lane >> 2;
    const int tid4 = lane & 3;
    const int wR = warp / WCOLS;
    const int wC = warp % WCOLS;
    const int rowBase = blockIdx.y * BM;
    const int colBase = blockIdx.x * BN;

    float acc[2][8][4];
#pragma unroll
    for (int i = 0; i < 2; i++)
#pragma unroll
        for (int j = 0; j < 8; j++)
#pragma unroll
            for (int q = 0; q < 4; q++) acc[i][j][q] = 0.f;

    const int chunks = K >> 5;

    auto load_stage = [&](int st, int c) {
        __nv_bfloat16* dAh = smem + st * STAGE;
        __nv_bfloat16* dAl = dAh + BM * STR;
        __nv_bfloat16* dBh = dAl + BM * STR;
        __nv_bfloat16* dBl = dBh + BN * STR;
        // A: BM rows x 4 x 16B   (BM*4 / 256 = 2 or 4 iters)
#pragma unroll
        for (int v = tid; v < BM * 4; v += 256) {
            int r = v >> 2, c4 = v & 3;
            int gr = rowBase + r;
            int sz = (gr < M) ? 16 : 0;
            size_t gi = (size_t)gr * K + c * 32 + c4 * 8;
            cp16(smem_u32(dAh + r * STR + c4 * 8), &Ah[gi], sz);
            cp16(smem_u32(dAl + r * STR + c4 * 8), &Al[gi], sz);
        }
        // B: BN rows x 4 x 16B
#pragma unroll
        for (int v = tid; v < BN * 4; v += 256) {
            int r = v >> 2, c4 = v & 3;
            size_t gi = (size_t)(colBase + r) * K + c * 32 + c4 * 8;
            cp16(smem_u32(dBh + r * STR + c4 * 8), &Bh[gi], 16);
            cp16(smem_u32(dBl + r * STR + c4 * 8), &Bl[gi], 16);
        }
    };

    load_stage(0, 0);
    CP_COMMIT();

    for (int c = 0; c < chunks; c++) {
        if (c + 1 < chunks) {
            load_stage((c + 1) & 1, c + 1);
            CP_COMMIT();
            CP_WAIT(1);
        } else {
            CP_WAIT(0);
        }
        __syncthreads();

        const __nv_bfloat16* sAh = smem + (c & 1) * STAGE;
        const __nv_bfloat16* sAl = sAh + BM * STR;
        const __nv_bfloat16* sBh = sAl + BM * STR;
        const __nv_bfloat16* sBl = sBh + BN * STR;

#pragma unroll
        for (int ks = 0; ks < 2; ks++) {
            const int kb = ks * 16 + tid4 * 2;
            uint32_t ah[2][4], al[2][4];
#pragma unroll
            for (int mf = 0; mf < 2; mf++) {
                int r0 = wR * 32 + mf * 16 + gid;
                ah[mf][0] = *(const uint32_t*)&sAh[r0 * STR + kb];
                ah[mf][1] = *(const uint32_t*)&sAh[(r0 + 8) * STR + kb];
                ah[mf][2] = *(const uint32_t*)&sAh[r0 * STR + kb + 8];
                ah[mf][3] = *(const uint32_t*)&sAh[(r0 + 8) * STR + kb + 8];
                al[mf][0] = *(const uint32_t*)&sAl[r0 * STR + kb];
                al[mf][1] = *(const uint32_t*)&sAl[(r0 + 8) * STR + kb];
                al[mf][2] = *(const uint32_t*)&sAl[r0 * STR + kb + 8];
                al[mf][3] = *(const uint32_t*)&sAl[(r0 + 8) * STR + kb + 8];
            }
#pragma unroll
            for (int nf = 0; nf < 8; nf++) {
                int n = wC * 64 + nf * 8 + gid;
                uint32_t bh[2], bl[2];
                bh[0] = *(const uint32_t*)&sBh[n * STR + kb];
                bh[1] = *(const uint32_t*)&sBh[n * STR + kb + 8];
                bl[0] = *(const uint32_t*)&sBl[n * STR + kb];
                bl[1] = *(const uint32_t*)&sBl[n * STR + kb + 8];
#pragma unroll
                for (int mf = 0; mf < 2; mf++) {
                    mma16816(acc[mf][nf], ah[mf], bh);
                    mma16816(acc[mf][nf], ah[mf], bl);
                    mma16816(acc[mf][nf], al[mf], bh);
                }
            }
        }
        __syncthreads();
    }

    // epilogue: bias + act (+ bf16 split), straight from fragments
#pragma unroll
    for (int nf = 0; nf < 8; nf++) {
        int col = colBase + wC * 64 + nf * 8 + tid4 * 2;
        float b0 = bias[col], b1 = bias[col + 1];
#pragma unroll
        for (int mf = 0; mf < 2; mf++) {
#pragma unroll
            for (int half = 0; half < 2; half++) {
                int row = rowBase + wR * 32 + mf * 16 + gid + half * 8;
                if (row >= M) continue;
                float v0 = acc[mf][nf][half * 2] + b0;
                float v1 = acc[mf][nf][half * 2 + 1] + b1;
                if (ACT == 1) { v0 = fmaxf(v0, 0.f); v1 = fmaxf(v1, 0.f); }
                size_t oi = (size_t)row * Nn + col;
                if (WF32) *(float2*)&Cf[oi] = make_float2(v0, v1);
                if (WB16) {
                    __nv_bfloat162 hh2, ll2;
                    split_bf16(v0, hh2.x, ll2.x);
                    split_bf16(v1, hh2.y, ll2.y);
                    *(__nv_bfloat162*)&Ch[oi] = hh2;
                    *(__nv_bfloat162*)&Cl[oi] = ll2;
                }
            }
        }
    }
}

// ================= fused GATv2 layer =========================================
// xlr: [NN][512], xl = cols 0..255, xr = cols 256..511
template <bool WB16>
__global__ __launch_bounds__(128)
void k_gat(const int* __restrict__ EI,
           const float* __restrict__ xlr,
           const float* __restrict__ att, const float* __restrict__ bias,
           float* __restrict__ out, __nv_bfloat16* outH, __nv_bfloat16* outL) {
    const int i = blockIdx.x;
    const int w = threadIdx.x >> 5;
    const int lane = threadIdx.x & 31;
    const int f = w * HID + lane * 2;
    const int s0 = g_off[i], s1 = g_off[i + 1];

    const float2 xrv = *(const float2*)(xlr + (size_t)i * 512 + 256 + f);
    const float2 atv = *(const float2*)(att + f);

    float acc0 = 0.f, acc1 = 0.f, den = 0.f;
    for (int p = s0; p < s1; p++) {
        int e = g_eid[p];
        int src = (e < EE) ? EI[e] : (e - EE);
        float2 xv = *(const float2*)(xlr + (size_t)src * 512 + f);
        float v0 = xv.x + xrv.x; v0 = v0 > 0.f ? v0 : 0.2f * v0;
        float v1 = xv.y + xrv.y; v1 = v1 > 0.f ? v1 : 0.2f * v1;
        float s = v0 * atv.x + v1 * atv.y;
#pragma unroll
        for (int o = 16; o; o >>= 1) s += __shfl_xor_sync(0xffffffffu, s, o);
        float ex = __expf(s);
        acc0 += ex * xv.x; acc1 += ex * xv.y; den += ex;
    }
    float rr = 1.f / (den + 1e-16f);
    float o0 = fmaxf(acc0 * rr + bias[f], 0.f);
    float o1 = fmaxf(acc1 * rr + bias[f + 1], 0.f);
    size_t oi = (size_t)i * DD + f;
    out[oi] = o0; out[oi + 1] = o1;
    if (WB16) {
        __nv_bfloat162 h, l;
        split_bf16(o0, h.x, l.x); split_bf16(o1, h.y, l.y);
        *(__nv_bfloat162*)&outH[oi] = h;
        *(__nv_bfloat162*)&outL[oi] = l;
    }
}

// ================= gather + dueling head =====================================
__global__ void k_feat(const int* __restrict__ idx,
                       const float* __restrict__ h,
                       const float* __restrict__ h2,
                       const float* __restrict__ h3) {
    int b = blockIdx.x, t = threadIdx.x;
    int n = idx[b];
    float v;
    if (t < HID)            v = h[(size_t)n * HID + t];
    else if (t < HID + DD)  v = h2[(size_t)n * DD + (t - HID)];
    else                    v = h3[(size_t)n * DD + (t - HID - DD)];
    g_feat[(size_t)b * CAT + t] = v;
}

__global__ void k_head(const float* __restrict__ qw1, const float* __restrict__ qb1,
                       const float* __restrict__ qw2, const float* __restrict__ qb2,
                       const float* __restrict__ vw1, const float* __restrict__ vb1,
                       const float* __restrict__ vw2, const float* __restrict__ vb2,
                       float* __restrict__ out) {
    __shared__ float f[CAT];
    __shared__ float r0[DUEL_H], r1[DUEL_H], r2[DUEL_H];
    int b = blockIdx.x, t = threadIdx.x;
    for (int i = t; i < CAT; i += DUEL_H) f[i] = g_feat[(size_t)b * CAT + i];
    __syncthreads();
    float q = 0.f, v = 0.f;
#pragma unroll 4
    for (int k = 0; k < CAT; k++) {
        float fv = f[k];
        q += fv * qw1[(size_t)k * DUEL_H + t];
        v += fv * vw1[(size_t)k * DUEL_H + t];
    }
    q = fmaxf(q + qb1[t], 0.f);
    v = fmaxf(v + vb1[t], 0.f);
    r0[t] = q * qw2[t * 2 + 0];
    r1[t] = q * qw2[t * 2 + 1];
    r2[t] = v * vw2[t];
    __syncthreads();
    for (int o = 64; o; o >>= 1) {
        if (t < o) { r0[t] += r0[t + o]; r1[t] += r1[t + o]; r2[t] += r2[t + o]; }
        __syncthreads();
    }
    if (t == 0) {
        float q0 = r0[0] + qb2[0], q1 = r1[0] + qb2[1], vv = r2[0] + vb2[0];
        float m = 0.5f * (q0 + q1);
        out[b * 2 + 0] = q0 - m + vv;
        out[b * 2 + 1] = q1 - m + vv;
    }
}

// ================= launch ====================================================
extern "C" void kernel_launch(void* const* d_in, const int* in_sizes, int n_in,
                              void* d_out, int out_size) {
    const float* x      = (const float*)d_in[0];
    const int*   EI     = (const int*)  d_in[1];
    const int*   idx    = (const int*)  d_in[2];
    const float* enc_w1 = (const float*)d_in[3];
    const float* enc_b1 = (const float*)d_in[4];
    const float* enc_w2 = (const float*)d_in[5];
    const float* enc_b2 = (const float*)d_in[6];
    const float* wl1    = (const float*)d_in[7];
    const float* bl1    = (const float*)d_in[8];
    const float* wr1    = (const float*)d_in[9];
    const float* br1    = (const float*)d_in[10];
    const float* att1   = (const float*)d_in[11];
    const float* bias1  = (const float*)d_in[12];
    const float* wl2    = (const float*)d_in[13];
    const float* bl2    = (const float*)d_in[14];
    const float* wr2    = (const float*)d_in[15];
    const float* br2    = (const float*)d_in[16];
    const float* att2   = (const float*)d_in[17];
    const float* bias2  = (const float*)d_in[18];
    const float* q_w1   = (const float*)d_in[19];
    const float* q_b1   = (const float*)d_in[20];
    const float* q_w2   = (const float*)d_in[21];
    const float* q_b2   = (const float*)d_in[22];
    const float* v_w1   = (const float*)d_in[23];
    const float* v_b1   = (const float*)d_in[24];
    const float* v_w2   = (const float*)d_in[25];
    const float* v_b2   = (const float*)d_in[26];
    float* out = (float*)d_out;

    float *h, *xlr, *h2, *h3, *b1, *b2;
    __nv_bfloat16 *xh, *xlo, *h512h, *h512l, *hh, *hl, *h2h, *h2l, *wth, *wtl;
    cudaGetSymbolAddress((void**)&h,    g_h);
    cudaGetSymbolAddress((void**)&xlr,  g_xlr);
    cudaGetSymbolAddress((void**)&h2,   g_h2);
    cudaGetSymbolAddress((void**)&h3,   g_h3);
    cudaGetSymbolAddress((void**)&b1,   g_b1);
    cudaGetSymbolAddress((void**)&b2,   g_b2);
    cudaGetSymbolAddress((void**)&xh,   g_xh);
    cudaGetSymbolAddress((void**)&xlo,  g_xlo);
    cudaGetSymbolAddress((void**)&h512h, g_h512h);
    cudaGetSymbolAddress((void**)&h512l, g_h512l);
    cudaGetSymbolAddress((void**)&hh,   g_hh);
    cudaGetSymbolAddress((void**)&hl,   g_hl);
    cudaGetSymbolAddress((void**)&h2h,  g_h2h);
    cudaGetSymbolAddress((void**)&h2l,  g_h2l);
    cudaGetSymbolAddress((void**)&wth,  g_wth);
    cudaGetSymbolAddress((void**)&wtl,  g_wtl);

    const int SM_BN128 = 2 * (2 * 128 + 2 * 128) * STR * 2;   // 81,920 B
    const int SM_BN64  = 2 * (2 * 256 + 2 * 64) * STR * 2;    // 102,400 B
    cudaFuncSetAttribute((const void*)k_mma<128, 1, 0, 1>, cudaFuncAttributeMaxDynamicSharedMemorySize, SM_BN128);
    cudaFuncSetAttribute((const void*)k_mma<64, 1, 1, 1>,  cudaFuncAttributeMaxDynamicSharedMemorySize, SM_BN64);
    cudaFuncSetAttribute((const void*)k_mma<128, 0, 1, 0>, cudaFuncAttributeMaxDynamicSharedMemorySize, SM_BN128);

    const int MT128 = (NN + 127) / 128;   // 157
    const int MT256 = (NN + 255) / 256;   // 79

    // prep
    k_split_x<<<(NN * HID + 255) / 256, 256>>>(x);
    k_wprep<<<896, 256>>>(enc_w1, enc_w2, wl1, wr1, wl2, wr2);
    k_bprep<<<4, 256>>>(bl1, br1, bl2, br2);
    k_zero_deg<<<(NN + 255) / 256, 256>>>();

    // enc1: [NN,64] @ [64,512] -> h512 (bf16 hi/lo), relu
    k_mma<128, 1, 0, 1><<<dim3(ENC_H / 128, MT128), 256, SM_BN128>>>(
        xh, xlo, wth + WOFF_ENC1, wtl + WOFF_ENC1, enc_b1, nullptr, h512h, h512l, NN, 64, ENC_H);
    k_count<<<(EP + 255) / 256, 256>>>(EI);
    // enc2: [NN,512] @ [512,64] -> h (f32 + bf16 hi/lo), relu
    k_mma<64, 1, 1, 1><<<dim3(1, MT256), 256, SM_BN64>>>(
        h512h, h512l, wth + WOFF_ENC2, wtl + WOFF_ENC2, enc_b2, h, hh, hl, NN, ENC_H, HID);
    k_scan<<<1, 1024>>>();
    k_fill<<<(EP + 255) / 256, 256>>>(EI);

    // conv1: combined [xl|xr] transform, N=512
    k_mma<128, 0, 1, 0><<<dim3(4, MT128), 256, SM_BN128>>>(
        hh, hl, wth + WOFF_W1, wtl + WOFF_W1, b1, xlr, nullptr, nullptr, NN, HID, 512);
    k_gat<true><<<NN, 128>>>(EI, xlr, att1, bias1, h2, h2h, h2l);

    // conv2: combined transform, N=512, K=256
    k_mma<128, 0, 1, 0><<<dim3(4, MT128), 256, SM_BN128>>>(
        h2h, h2l, wth + WOFF_W2, wtl + WOFF_W2, b2, xlr, nullptr, nullptr, NN, DD, 512);
    k_gat<false><<<NN, 128>>>(EI, xlr, att2, bias2, h3, nullptr, nullptr);

    // heads
    k_feat<<<BB, CAT>>>(idx, h, h2, h3);
    k_head<<<BB, DUEL_H>>>(q_w1, q_b1, q_w2, q_b2, v_w1, v_b1, v_w2, v_b2, out);
}

// round 7
// speedup vs baseline: 2.5200x; 1.0533x over previous
#include <cuda_runtime.h>
#include <cuda_bf16.h>
#include <cstdint>

// Problem constants
#define NN 20000
#define EE 320000
#define EP (EE + NN)          // 340000
#define BB 128
#define HID 64
#define HEADS 4
#define DD 256
#define CAT 576
#define ENC_H 512
#define DUEL_H 128

// ================= scratch (static device memory) ============================
__device__ float g_h[NN * HID];
__device__ float g_xlr[NN * 512];     // [xl | xr] per row
__device__ float g_h2[NN * DD];
__device__ float g_h3[NN * DD];
__device__ float g_b1[512], g_b2[512];  // pooled conv biases [bl | br]
__device__ int   g_deg[NN];
__device__ int   g_off[NN + 1];
__device__ int   g_pos[NN];
__device__ int   g_src[EP];           // CSR payload: source node id (direct)
// bf16 hi/lo activations
__device__ __nv_bfloat16 g_xh[NN * HID],      g_xlo[NN * HID];
__device__ __nv_bfloat16 g_h512h[NN * ENC_H], g_h512l[NN * ENC_H];
__device__ __nv_bfloat16 g_hh[NN * HID],      g_hl[NN * HID];
__device__ __nv_bfloat16 g_h2h[NN * DD],      g_h2l[NN * DD];
// transposed bf16 hi/lo weights, packed pool  (layout [N][K]); WL/WR pairs contiguous
#define WOFF_ENC1 0          // [512][64]
#define WOFF_ENC2 32768      // [64][512]
#define WOFF_W1   65536      // [512][64]  (wl1 || wr1)
#define WOFF_W2   98304      // [512][256] (wl2 || wr2)
#define WPOOL     229376
__device__ __nv_bfloat16 g_wth[WPOOL], g_wtl[WPOOL];

__device__ __forceinline__ void split_bf16(float v, __nv_bfloat16& hi, __nv_bfloat16& lo) {
    hi = __float2bfloat16(v);
    lo = __float2bfloat16(v - __bfloat162float(hi));
}

__device__ __forceinline__ uint32_t smem_u32(const void* p) {
    uint32_t a;
    asm("{ .reg .u64 t; cvta.to.shared.u64 t, %1; cvt.u32.u64 %0, t; }" : "=r"(a) : "l"(p));
    return a;
}
__device__ __forceinline__ void cp16(uint32_t d, const void* s, int sz) {
    asm volatile("cp.async.cg.shared.global [%0], [%1], 16, %2;" :: "r"(d), "l"(s), "r"(sz));
}
#define CP_COMMIT() asm volatile("cp.async.commit_group;" ::: "memory")
#define CP_WAIT(n)  asm volatile("cp.async.wait_group %0;" :: "n"(n) : "memory")

// bf16 mma.sync (sm_80+ baseline; valid on plain sm_103 target)
__device__ __forceinline__ void mma16816(float* c, const uint32_t* a, const uint32_t* b) {
    asm volatile(
        "mma.sync.aligned.m16n8k16.row.col.f32.bf16.bf16.f32 "
        "{%0,%1,%2,%3}, {%4,%5,%6,%7}, {%8,%9}, {%0,%1,%2,%3};"
        : "+f"(c[0]), "+f"(c[1]), "+f"(c[2]), "+f"(c[3])
        : "r"(a[0]), "r"(a[1]), "r"(a[2]), "r"(a[3]), "r"(b[0]), "r"(b[1]));
}

// ================= prep kernels ==============================================
__global__ void k_split_x(const float* __restrict__ x) {
    int i = blockIdx.x * blockDim.x + threadIdx.x;
    if (i < NN) g_deg[i] = 0;                 // fold zero_deg in
    if (i >= NN * HID) return;
    split_bf16(x[i], g_xh[i], g_xlo[i]);
}

__global__ void k_wprep(const float* __restrict__ w0, const float* __restrict__ w1,
                        const float* __restrict__ w2, const float* __restrict__ w3,
                        const float* __restrict__ w4, const float* __restrict__ w5) {
    int blk = blockIdx.x;
    const float* src; int K_, N_, dst, start;
    if      (blk < 128) { src = w0; K_ = 64;  N_ = 512; dst = WOFF_ENC1;        start = 0;   }
    else if (blk < 256) { src = w1; K_ = 512; N_ = 64;  dst = WOFF_ENC2;        start = 128; }
    else if (blk < 320) { src = w2; K_ = 64;  N_ = 256; dst = WOFF_W1;          start = 256; }
    else if (blk < 384) { src = w3; K_ = 64;  N_ = 256; dst = WOFF_W1 + 16384;  start = 320; }
    else if (blk < 640) { src = w4; K_ = 256; N_ = 256; dst = WOFF_W2;          start = 384; }
    else                { src = w5; K_ = 256; N_ = 256; dst = WOFF_W2 + 65536;  start = 640; }
    int e = (blk - start) * 256 + threadIdx.x;
    if (e >= K_ * N_) return;
    int n = e / K_, k = e % K_;
    split_bf16(src[(size_t)k * N_ + n], g_wth[dst + e], g_wtl[dst + e]);
}

__global__ void k_bprep(const float* __restrict__ bl1, const float* __restrict__ br1,
                        const float* __restrict__ bl2, const float* __restrict__ br2) {
    int t = blockIdx.x * blockDim.x + threadIdx.x;
    if (t >= 1024) return;
    if (t < 256)       g_b1[t] = bl1[t];
    else if (t < 512)  g_b1[t] = br1[t - 256];
    else if (t < 768)  g_b2[t - 512] = bl2[t - 512];
    else               g_b2[t - 512] = br2[t - 768];
}

// ================= CSR build ================================================
__global__ void k_count(const int* __restrict__ EI) {
    int e = blockIdx.x * blockDim.x + threadIdx.x;
    if (e >= EP) return;
    int dst = (e < EE) ? EI[EE + e] : (e - EE);
    atomicAdd(&g_deg[dst], 1);
}
__global__ void k_scan() {
    const int CH = (NN + 1023) / 1024;
    __shared__ int part[1024];
    int t = threadIdx.x, base = t * CH, local[CH], s = 0;
#pragma unroll
    for (int i = 0; i < CH; i++) {
        int idx = base + i;
        int v = (idx < NN) ? g_deg[idx] : 0;
        local[i] = s; s += v;
    }
    part[t] = s;
    __syncthreads();
    for (int o = 1; o < 1024; o <<= 1) {
        int v = (t >= o) ? part[t - o] : 0;
        __syncthreads();
        part[t] += v;
        __syncthreads();
    }
    int ex0 = (t == 0) ? 0 : part[t - 1];
#pragma unroll
    for (int i = 0; i < CH; i++) {
        int idx = base + i;
        if (idx < NN) { int v = ex0 + local[i]; g_off[idx] = v; g_pos[idx] = v; }
    }
    if (t == 1023) g_off[NN] = ex0 + s;
}
__global__ void k_fill(const int* __restrict__ EI) {
    int e = blockIdx.x * blockDim.x + threadIdx.x;
    if (e >= EP) return;
    int dst, src;
    if (e < EE) { src = EI[e]; dst = EI[EE + e]; }
    else        { src = dst = e - EE; }
    int p = atomicAdd(&g_pos[dst], 1);
    g_src[p] = src;
}

// ================= HMMA GEMM (cp.async 2-stage pipeline) =====================
// C[M,Nn] = act(A @ W + b). A bf16 hi/lo [M][K]; W transposed bf16 hi/lo [Nn][K].
// 3-pass split AhWh + AhWl + AlWh, fp32 accum. 256 threads = 8 warps.
// Warp grid: WROWS = BM/32 rows x WCOLS = 8/WROWS cols. BK=32. STR=40.
#define STR 40
template <int BM, int BN, int ACT, int WF32, int WB16>
__global__ __launch_bounds__(256, 2)
void k_mma(const __nv_bfloat16* __restrict__ Ah, const __nv_bfloat16* __restrict__ Al,
           const __nv_bfloat16* __restrict__ Bh, const __nv_bfloat16* __restrict__ Bl,
           const float* __restrict__ bias, float* __restrict__ Cf,
           __nv_bfloat16* __restrict__ Ch, __nv_bfloat16* __restrict__ Cl,
           int M, int K, int Nn) {
    constexpr int WROWS = BM / 32;
    constexpr int WCOLS = 8 / WROWS;
    constexpr int WNT = BN / WCOLS;     // warp n-tile
    constexpr int NF = WNT / 8;         // n-frags per warp
    constexpr int STAGE = (2 * BM + 2 * BN) * STR;
    extern __shared__ __nv_bfloat16 smem[];

    const int tid = threadIdx.x;
    const int warp = tid >> 5;
    const int lane = tid & 31;
    const int gid = lane >> 2;
    const int tid4 = lane & 3;
    const int wR = warp / WCOLS;
    const int wC = warp % WCOLS;
    const int rowBase = blockIdx.y * BM;
    const int colBase = blockIdx.x * BN;

    float acc[2][NF][4];
#pragma unroll
    for (int i = 0; i < 2; i++)
#pragma unroll
        for (int j = 0; j < NF; j++)
#pragma unroll
            for (int q = 0; q < 4; q++) acc[i][j][q] = 0.f;

    const int chunks = K >> 5;

    auto load_stage = [&](int st, int c) {
        __nv_bfloat16* dAh = smem + st * STAGE;
        __nv_bfloat16* dAl = dAh + BM * STR;
        __nv_bfloat16* dBh = dAl + BM * STR;
        __nv_bfloat16* dBl = dBh + BN * STR;
#pragma unroll
        for (int v = tid; v < BM * 4; v += 256) {
            int r = v >> 2, c4 = v & 3;
            int gr = rowBase + r;
            int sz = (gr < M) ? 16 : 0;
            size_t gi = (size_t)gr * K + c * 32 + c4 * 8;
            cp16(smem_u32(dAh + r * STR + c4 * 8), &Ah[gi], sz);
            cp16(smem_u32(dAl + r * STR + c4 * 8), &Al[gi], sz);
        }
#pragma unroll
        for (int v = tid; v < BN * 4; v += 256) {
            int r = v >> 2, c4 = v & 3;
            size_t gi = (size_t)(colBase + r) * K + c * 32 + c4 * 8;
            cp16(smem_u32(dBh + r * STR + c4 * 8), &Bh[gi], 16);
            cp16(smem_u32(dBl + r * STR + c4 * 8), &Bl[gi], 16);
        }
    };

    load_stage(0, 0);
    CP_COMMIT();

    for (int c = 0; c < chunks; c++) {
        if (c + 1 < chunks) {
            load_stage((c + 1) & 1, c + 1);
            CP_COMMIT();
            CP_WAIT(1);
        } else {
            CP_WAIT(0);
        }
        __syncthreads();

        const __nv_bfloat16* sAh = smem + (c & 1) * STAGE;
        const __nv_bfloat16* sAl = sAh + BM * STR;
        const __nv_bfloat16* sBh = sAl + BM * STR;
        const __nv_bfloat16* sBl = sBh + BN * STR;

#pragma unroll
        for (int ks = 0; ks < 2; ks++) {
            const int kb = ks * 16 + tid4 * 2;
            uint32_t ah[2][4], al[2][4];
#pragma unroll
            for (int mf = 0; mf < 2; mf++) {
                int r0 = wR * 32 + mf * 16 + gid;
                ah[mf][0] = *(const uint32_t*)&sAh[r0 * STR + kb];
                ah[mf][1] = *(const uint32_t*)&sAh[(r0 + 8) * STR + kb];
                ah[mf][2] = *(const uint32_t*)&sAh[r0 * STR + kb + 8];
                ah[mf][3] = *(const uint32_t*)&sAh[(r0 + 8) * STR + kb + 8];
                al[mf][0] = *(const uint32_t*)&sAl[r0 * STR + kb];
                al[mf][1] = *(const uint32_t*)&sAl[(r0 + 8) * STR + kb];
                al[mf][2] = *(const uint32_t*)&sAl[r0 * STR + kb + 8];
                al[mf][3] = *(const uint32_t*)&sAl[(r0 + 8) * STR + kb + 8];
            }
#pragma unroll
            for (int nf = 0; nf < NF; nf++) {
                int n = wC * WNT + nf * 8 + gid;
                uint32_t bh[2], bl[2];
                bh[0] = *(const uint32_t*)&sBh[n * STR + kb];
                bh[1] = *(const uint32_t*)&sBh[n * STR + kb + 8];
                bl[0] = *(const uint32_t*)&sBl[n * STR + kb];
                bl[1] = *(const uint32_t*)&sBl[n * STR + kb + 8];
#pragma unroll
                for (int mf = 0; mf < 2; mf++) {
                    mma16816(acc[mf][nf], ah[mf], bh);
                    mma16816(acc[mf][nf], ah[mf], bl);
                    mma16816(acc[mf][nf], al[mf], bh);
                }
            }
        }
        __syncthreads();
    }

    // epilogue: bias + act (+ bf16 split), straight from fragments
#pragma unroll
    for (int nf = 0; nf < NF; nf++) {
        int col = colBase + wC * WNT + nf * 8 + tid4 * 2;
        float b0 = bias[col], b1 = bias[col + 1];
#pragma unroll
        for (int mf = 0; mf < 2; mf++) {
#pragma unroll
            for (int half = 0; half < 2; half++) {
                int row = rowBase + wR * 32 + mf * 16 + gid + half * 8;
                if (row >= M) continue;
                float v0 = acc[mf][nf][half * 2] + b0;
                float v1 = acc[mf][nf][half * 2 + 1] + b1;
                if (ACT == 1) { v0 = fmaxf(v0, 0.f); v1 = fmaxf(v1, 0.f); }
                size_t oi = (size_t)row * Nn + col;
                if (WF32) *(float2*)&Cf[oi] = make_float2(v0, v1);
                if (WB16) {
                    __nv_bfloat162 hh2, ll2;
                    split_bf16(v0, hh2.x, ll2.x);
                    split_bf16(v1, hh2.y, ll2.y);
                    *(__nv_bfloat162*)&Ch[oi] = hh2;
                    *(__nv_bfloat162*)&Cl[oi] = ll2;
                }
            }
        }
    }
}

// ================= fused GATv2 layer (prefetch-pipelined) =====================
// xlr: [NN][512], xl = cols 0..255, xr = cols 256..511
template <bool WB16>
__global__ __launch_bounds__(128)
void k_gat(const float* __restrict__ xlr,
           const float* __restrict__ att, const float* __restrict__ bias,
           float* __restrict__ out, __nv_bfloat16* outH, __nv_bfloat16* outL) {
    const int i = blockIdx.x;
    const int w = threadIdx.x >> 5;
    const int lane = threadIdx.x & 31;
    const int f = w * HID + lane * 2;
    const int s0 = g_off[i], s1 = g_off[i + 1];   // s1 > s0 (self loop)

    const float2 xrv = *(const float2*)(xlr + (size_t)i * 512 + 256 + f);
    const float2 atv = *(const float2*)(att + f);

    float acc0 = 0.f, acc1 = 0.f, den = 0.f;
    int srcA = __ldg(&g_src[s0]);
    float2 xvA = *(const float2*)(xlr + (size_t)srcA * 512 + f);
    for (int p = s0; p < s1; p++) {
        // prefetch next edge while this one's reduce chain drains
        float2 xvB = xvA;
        if (p + 1 < s1) {
            int srcB = __ldg(&g_src[p + 1]);
            xvB = *(const float2*)(xlr + (size_t)srcB * 512 + f);
        }
        float v0 = xvA.x + xrv.x; v0 = v0 > 0.f ? v0 : 0.2f * v0;
        float v1 = xvA.y + xrv.y; v1 = v1 > 0.f ? v1 : 0.2f * v1;
        float s = v0 * atv.x + v1 * atv.y;
#pragma unroll
        for (int o = 16; o; o >>= 1) s += __shfl_xor_sync(0xffffffffu, s, o);
        float ex = __expf(s);
        acc0 += ex * xvA.x; acc1 += ex * xvA.y; den += ex;
        xvA = xvB;
    }
    float rr = 1.f / (den + 1e-16f);
    float o0 = fmaxf(acc0 * rr + bias[f], 0.f);
    float o1 = fmaxf(acc1 * rr + bias[f + 1], 0.f);
    size_t oi = (size_t)i * DD + f;
    out[oi] = o0; out[oi + 1] = o1;
    if (WB16) {
        __nv_bfloat162 h, l;
        split_bf16(o0, h.x, l.x); split_bf16(o1, h.y, l.y);
        *(__nv_bfloat162*)&outH[oi] = h;
        *(__nv_bfloat162*)&outL[oi] = l;
    }
}

// ================= dueling head (feat gather fused) ==========================
__global__ void k_head(const int* __restrict__ idx,
                       const float* __restrict__ h,
                       const float* __restrict__ h2,
                       const float* __restrict__ h3,
                       const float* __restrict__ qw1, const float* __restrict__ qb1,
                       const float* __restrict__ qw2, const float* __restrict__ qb2,
                       const float* __restrict__ vw1, const float* __restrict__ vb1,
                       const float* __restrict__ vw2, const float* __restrict__ vb2,
                       float* __restrict__ out) {
    __shared__ float f[CAT];
    __shared__ float r0[DUEL_H], r1[DUEL_H], r2[DUEL_H];
    int b = blockIdx.x, t = threadIdx.x;
    int n = idx[b];
    for (int i = t; i < CAT; i += DUEL_H) {
        float v;
        if (i < HID)            v = h[(size_t)n * HID + i];
        else if (i < HID + DD)  v = h2[(size_t)n * DD + (i - HID)];
        else                    v = h3[(size_t)n * DD + (i - HID - DD)];
        f[i] = v;
    }
    __syncthreads();
    float q = 0.f, v = 0.f;
#pragma unroll 4
    for (int k = 0; k < CAT; k++) {
        float fv = f[k];
        q += fv * qw1[(size_t)k * DUEL_H + t];
        v += fv * vw1[(size_t)k * DUEL_H + t];
    }
    q = fmaxf(q + qb1[t], 0.f);
    v = fmaxf(v + vb1[t], 0.f);
    r0[t] = q * qw2[t * 2 + 0];
    r1[t] = q * qw2[t * 2 + 1];
    r2[t] = v * vw2[t];
    __syncthreads();
    for (int o = 64; o; o >>= 1) {
        if (t < o) { r0[t] += r0[t + o]; r1[t] += r1[t + o]; r2[t] += r2[t + o]; }
        __syncthreads();
    }
    if (t == 0) {
        float q0 = r0[0] + qb2[0], q1 = r1[0] + qb2[1], vv = r2[0] + vb2[0];
        float m = 0.5f * (q0 + q1);
        out[b * 2 + 0] = q0 - m + vv;
        out[b * 2 + 1] = q1 - m + vv;
    }
}

// ================= launch ====================================================
extern "C" void kernel_launch(void* const* d_in, const int* in_sizes, int n_in,
                              void* d_out, int out_size) {
    const float* x      = (const float*)d_in[0];
    const int*   EI     = (const int*)  d_in[1];
    const int*   idx    = (const int*)  d_in[2];
    const float* enc_w1 = (const float*)d_in[3];
    const float* enc_b1 = (const float*)d_in[4];
    const float* enc_w2 = (const float*)d_in[5];
    const float* enc_b2 = (const float*)d_in[6];
    const float* wl1    = (const float*)d_in[7];
    const float* bl1    = (const float*)d_in[8];
    const float* wr1    = (const float*)d_in[9];
    const float* br1    = (const float*)d_in[10];
    const float* att1   = (const float*)d_in[11];
    const float* bias1  = (const float*)d_in[12];
    const float* wl2    = (const float*)d_in[13];
    const float* bl2    = (const float*)d_in[14];
    const float* wr2    = (const float*)d_in[15];
    const float* br2    = (const float*)d_in[16];
    const float* att2   = (const float*)d_in[17];
    const float* bias2  = (const float*)d_in[18];
    const float* q_w1   = (const float*)d_in[19];
    const float* q_b1   = (const float*)d_in[20];
    const float* q_w2   = (const float*)d_in[21];
    const float* q_b2   = (const float*)d_in[22];
    const float* v_w1   = (const float*)d_in[23];
    const float* v_b1   = (const float*)d_in[24];
    const float* v_w2   = (const float*)d_in[25];
    const float* v_b2   = (const float*)d_in[26];
    float* out = (float*)d_out;

    float *h, *xlr, *h2, *h3, *b1, *b2;
    __nv_bfloat16 *xh, *xlo, *h512h, *h512l, *hh, *hl, *h2h, *h2l, *wth, *wtl;
    cudaGetSymbolAddress((void**)&h,    g_h);
    cudaGetSymbolAddress((void**)&xlr,  g_xlr);
    cudaGetSymbolAddress((void**)&h2,   g_h2);
    cudaGetSymbolAddress((void**)&h3,   g_h3);
    cudaGetSymbolAddress((void**)&b1,   g_b1);
    cudaGetSymbolAddress((void**)&b2,   g_b2);
    cudaGetSymbolAddress((void**)&xh,   g_xh);
    cudaGetSymbolAddress((void**)&xlo,  g_xlo);
    cudaGetSymbolAddress((void**)&h512h, g_h512h);
    cudaGetSymbolAddress((void**)&h512l, g_h512l);
    cudaGetSymbolAddress((void**)&hh,   g_hh);
    cudaGetSymbolAddress((void**)&hl,   g_hl);
    cudaGetSymbolAddress((void**)&h2h,  g_h2h);
    cudaGetSymbolAddress((void**)&h2l,  g_h2l);
    cudaGetSymbolAddress((void**)&wth,  g_wth);
    cudaGetSymbolAddress((void**)&wtl,  g_wtl);

    const int SM_128_128 = 2 * (2 * 128 + 2 * 128) * STR * 2;   // 81,920 B
    const int SM_128_64  = 2 * (2 * 128 + 2 * 64) * STR * 2;    // 61,440 B
    cudaFuncSetAttribute((const void*)k_mma<128, 128, 1, 0, 1>, cudaFuncAttributeMaxDynamicSharedMemorySize, SM_128_128);
    cudaFuncSetAttribute((const void*)k_mma<128, 64, 1, 1, 1>,  cudaFuncAttributeMaxDynamicSharedMemorySize, SM_128_64);
    cudaFuncSetAttribute((const void*)k_mma<128, 128, 0, 1, 0>, cudaFuncAttributeMaxDynamicSharedMemorySize, SM_128_128);

    const int MT128 = (NN + 127) / 128;   // 157

    // prep
    k_split_x<<<(NN * HID + 255) / 256, 256>>>(x);
    k_wprep<<<896, 256>>>(enc_w1, enc_w2, wl1, wr1, wl2, wr2);
    k_bprep<<<4, 256>>>(bl1, br1, bl2, br2);

    // enc1: [NN,64] @ [64,512] -> h512 (bf16 hi/lo), relu
    k_mma<128, 128, 1, 0, 1><<<dim3(ENC_H / 128, MT128), 256, SM_128_128>>>(
        xh, xlo, wth + WOFF_ENC1, wtl + WOFF_ENC1, enc_b1, nullptr, h512h, h512l, NN, 64, ENC_H);
    k_count<<<(EP + 255) / 256, 256>>>(EI);
    // enc2: [NN,512] @ [512,64] -> h (f32 + bf16 hi/lo), relu
    k_mma<128, 64, 1, 1, 1><<<dim3(1, MT128), 256, SM_128_64>>>(
        h512h, h512l, wth + WOFF_ENC2, wtl + WOFF_ENC2, enc_b2, h, hh, hl, NN, ENC_H, HID);
    k_scan<<<1, 1024>>>();
    k_fill<<<(EP + 255) / 256, 256>>>(EI);

    // conv1: combined [xl|xr] transform, N=512
    k_mma<128, 128, 0, 1, 0><<<dim3(4, MT128), 256, SM_128_128>>>(
        hh, hl, wth + WOFF_W1, wtl + WOFF_W1, b1, xlr, nullptr, nullptr, NN, HID, 512);
    k_gat<true><<<NN, 128>>>(xlr, att1, bias1, h2, h2h, h2l);

    // conv2: combined transform, N=512, K=256
    k_mma<128, 128, 0, 1, 0><<<dim3(4, MT128), 256, SM_128_128>>>(
        h2h, h2l, wth + WOFF_W2, wtl + WOFF_W2, b2, xlr, nullptr, nullptr, NN, DD, 512);
    k_gat<false><<<NN, 128>>>(xlr, att2, bias2, h3, nullptr, nullptr);

    // heads (feat gather fused)
    k_head<<<BB, DUEL_H>>>(idx, h, h2, h3,
                           q_w1, q_b1, q_w2, q_b2, v_w1, v_b1, v_w2, v_b2, out);
}

// round 8
// speedup vs baseline: 2.6252x; 1.0418x over previous
#include <cuda_runtime.h>
#include <cuda_bf16.h>
#include <cstdint>

// Problem constants
#define NN 20000
#define EE 320000
#define EP (EE + NN)          // 340000
#define BB 128
#define HID 64
#define HEADS 4
#define DD 256
#define CAT 576
#define ENC_H 512
#define DUEL_H 128

// ================= scratch (static device memory) ============================
__device__ float g_h[NN * HID];
__device__ float g_xlr[NN * 512];     // [xl | xr] per row
__device__ float g_h2[NN * DD];
__device__ float g_h3[NN * DD];
__device__ float g_b1[512], g_b2[512];  // pooled conv biases [bl | br]
__device__ int   g_deg[NN];
__device__ int   g_off[NN + 1];
__device__ int   g_pos[NN];
__device__ int   g_src[EP];           // CSR payload: source node id (direct)
// bf16 hi/lo activations
__device__ __nv_bfloat16 g_xh[NN * HID],      g_xlo[NN * HID];
__device__ __nv_bfloat16 g_h512h[NN * ENC_H], g_h512l[NN * ENC_H];
__device__ __nv_bfloat16 g_hh[NN * HID],      g_hl[NN * HID];
__device__ __nv_bfloat16 g_h2h[NN * DD],      g_h2l[NN * DD];
// transposed bf16 hi/lo weights, packed pool  (layout [N][K]); WL/WR pairs contiguous
#define WOFF_ENC1 0          // [512][64]
#define WOFF_ENC2 32768      // [64][512]
#define WOFF_W1   65536      // [512][64]  (wl1 || wr1)
#define WOFF_W2   98304      // [512][256] (wl2 || wr2)
#define WPOOL     229376
__device__ __nv_bfloat16 g_wth[WPOOL], g_wtl[WPOOL];

__device__ __forceinline__ void split_bf16(float v, __nv_bfloat16& hi, __nv_bfloat16& lo) {
    hi = __float2bfloat16(v);
    lo = __float2bfloat16(v - __bfloat162float(hi));
}

__device__ __forceinline__ uint32_t smem_u32(const void* p) {
    uint32_t a;
    asm("{ .reg .u64 t; cvta.to.shared.u64 t, %1; cvt.u32.u64 %0, t; }" : "=r"(a) : "l"(p));
    return a;
}
__device__ __forceinline__ void cp16(uint32_t d, const void* s, int sz) {
    asm volatile("cp.async.cg.shared.global [%0], [%1], 16, %2;" :: "r"(d), "l"(s), "r"(sz));
}
#define CP_COMMIT() asm volatile("cp.async.commit_group;" ::: "memory")
#define CP_WAIT(n)  asm volatile("cp.async.wait_group %0;" :: "n"(n) : "memory")

// bf16 mma.sync + ldmatrix (sm_75/80+ baseline; valid on plain sm_103 target)
__device__ __forceinline__ void mma16816(float* c, const uint32_t* a, const uint32_t* b) {
    asm volatile(
        "mma.sync.aligned.m16n8k16.row.col.f32.bf16.bf16.f32 "
        "{%0,%1,%2,%3}, {%4,%5,%6,%7}, {%8,%9}, {%0,%1,%2,%3};"
        : "+f"(c[0]), "+f"(c[1]), "+f"(c[2]), "+f"(c[3])
        : "r"(a[0]), "r"(a[1]), "r"(a[2]), "r"(a[3]), "r"(b[0]), "r"(b[1]));
}
__device__ __forceinline__ void ldsm_x4(uint32_t* r, uint32_t addr) {
    asm volatile("ldmatrix.sync.aligned.m8n8.x4.shared.b16 {%0,%1,%2,%3}, [%4];"
        : "=r"(r[0]), "=r"(r[1]), "=r"(r[2]), "=r"(r[3]) : "r"(addr));
}

// ================= prep kernels ==============================================
__global__ void k_split_x(const float* __restrict__ x) {
    int i = blockIdx.x * blockDim.x + threadIdx.x;
    if (i < NN) g_deg[i] = 0;
    if (i >= NN * HID) return;
    split_bf16(x[i], g_xh[i], g_xlo[i]);
}

__global__ void k_wprep(const float* __restrict__ w0, const float* __restrict__ w1,
                        const float* __restrict__ w2, const float* __restrict__ w3,
                        const float* __restrict__ w4, const float* __restrict__ w5) {
    int blk = blockIdx.x;
    const float* src; int K_, N_, dst, start;
    if      (blk < 128) { src = w0; K_ = 64;  N_ = 512; dst = WOFF_ENC1;        start = 0;   }
    else if (blk < 256) { src = w1; K_ = 512; N_ = 64;  dst = WOFF_ENC2;        start = 128; }
    else if (blk < 320) { src = w2; K_ = 64;  N_ = 256; dst = WOFF_W1;          start = 256; }
    else if (blk < 384) { src = w3; K_ = 64;  N_ = 256; dst = WOFF_W1 + 16384;  start = 320; }
    else if (blk < 640) { src = w4; K_ = 256; N_ = 256; dst = WOFF_W2;          start = 384; }
    else                { src = w5; K_ = 256; N_ = 256; dst = WOFF_W2 + 65536;  start = 640; }
    int e = (blk - start) * 256 + threadIdx.x;
    if (e >= K_ * N_) return;
    int n = e / K_, k = e % K_;
    split_bf16(src[(size_t)k * N_ + n], g_wth[dst + e], g_wtl[dst + e]);
}

__global__ void k_bprep(const float* __restrict__ bl1, const float* __restrict__ br1,
                        const float* __restrict__ bl2, const float* __restrict__ br2) {
    int t = blockIdx.x * blockDim.x + threadIdx.x;
    if (t >= 1024) return;
    if (t < 256)       g_b1[t] = bl1[t];
    else if (t < 512)  g_b1[t] = br1[t - 256];
    else if (t < 768)  g_b2[t - 512] = bl2[t - 512];
    else               g_b2[t - 512] = br2[t - 768];
}

// ================= CSR build ================================================
__global__ void k_count(const int* __restrict__ EI) {
    int e = blockIdx.x * blockDim.x + threadIdx.x;
    if (e >= EP) return;
    int dst = (e < EE) ? EI[EE + e] : (e - EE);
    atomicAdd(&g_deg[dst], 1);
}
__global__ void k_scan() {
    const int CH = (NN + 1023) / 1024;
    __shared__ int part[1024];
    int t = threadIdx.x, base = t * CH, local[CH], s = 0;
#pragma unroll
    for (int i = 0; i < CH; i++) {
        int idx = base + i;
        int v = (idx < NN) ? g_deg[idx] : 0;
        local[i] = s; s += v;
    }
    part[t] = s;
    __syncthreads();
    for (int o = 1; o < 1024; o <<= 1) {
        int v = (t >= o) ? part[t - o] : 0;
        __syncthreads();
        part[t] += v;
        __syncthreads();
    }
    int ex0 = (t == 0) ? 0 : part[t - 1];
#pragma unroll
    for (int i = 0; i < CH; i++) {
        int idx = base + i;
        if (idx < NN) { int v = ex0 + local[i]; g_off[idx] = v; g_pos[idx] = v; }
    }
    if (t == 1023) g_off[NN] = ex0 + s;
}
__global__ void k_fill(const int* __restrict__ EI) {
    int e = blockIdx.x * blockDim.x + threadIdx.x;
    if (e >= EP) return;
    int dst, src;
    if (e < EE) { src = EI[e]; dst = EI[EE + e]; }
    else        { src = dst = e - EE; }
    int p = atomicAdd(&g_pos[dst], 1);
    g_src[p] = src;
}

// ================= HMMA GEMM (cp.async pipeline + ldmatrix) ==================
// C[M,Nn] = act(A @ W + b). A bf16 hi/lo [M][K]; W transposed bf16 hi/lo [Nn][K].
// 3-pass split AhWh + AhWl + AlWh, fp32 accum. 256 threads = 8 warps.
// Warp grid: WROWS = BM/32 rows x WCOLS = 8/WROWS cols. BK=32. STR=40 (LDSM
// conflict-free: i*20 mod 32 covers all bank groups).
#define STR 40
template <int BM, int BN, int ACT, int WF32, int WB16>
__global__ __launch_bounds__(256, 2)
void k_mma(const __nv_bfloat16* __restrict__ Ah, const __nv_bfloat16* __restrict__ Al,
           const __nv_bfloat16* __restrict__ Bh, const __nv_bfloat16* __restrict__ Bl,
           const float* __restrict__ bias, float* __restrict__ Cf,
           __nv_bfloat16* __restrict__ Ch, __nv_bfloat16* __restrict__ Cl,
           int M, int K, int Nn) {
    constexpr int WROWS = BM / 32;
    constexpr int WCOLS = 8 / WROWS;
    constexpr int WNT = BN / WCOLS;     // warp n-tile
    constexpr int NF = WNT / 8;         // n-frags per warp
    constexpr int STAGE = (2 * BM + 2 * BN) * STR;   // elements
    extern __shared__ __nv_bfloat16 smem[];

    const int tid = threadIdx.x;
    const int warp = tid >> 5;
    const int lane = tid & 31;
    const int gid = lane >> 2;
    const int tid4 = lane & 3;
    const int wR = warp / WCOLS;
    const int wC = warp % WCOLS;
    const int rowBase = blockIdx.y * BM;
    const int colBase = blockIdx.x * BN;

    // ldmatrix lane roles
    const int q = lane >> 3;          // quad 0..3
    const int ri = lane & 7;
    // A x4: quad -> (row += (q&1)*8, col += (q>>1)*8)
    const int aRow = wR * 32 + ri + (q & 1) * 8;
    const int aCol = (q >> 1) * 8;
    // B x4 (pair of n-frags): quad -> (n += (q>>1)*8, col += (q&1)*8)
    const int bRow = wC * WNT + ri + (q >> 1) * 8;
    const int bCol = (q & 1) * 8;

    const uint32_t sbase = smem_u32(smem);
    // element offsets of buffers within a stage
    constexpr int offAl = BM * STR;
    constexpr int offBh = 2 * BM * STR;
    constexpr int offBl = 2 * BM * STR + BN * STR;

    float acc[2][NF][4];
#pragma unroll
    for (int i = 0; i < 2; i++)
#pragma unroll
        for (int j = 0; j < NF; j++)
#pragma unroll
            for (int qq = 0; qq < 4; qq++) acc[i][j][qq] = 0.f;

    const int chunks = K >> 5;

    auto load_stage = [&](int st, int c) {
        __nv_bfloat16* dAh = smem + st * STAGE;
        __nv_bfloat16* dAl = dAh + BM * STR;
        __nv_bfloat16* dBh = dAl + BM * STR;
        __nv_bfloat16* dBl = dBh + BN * STR;
#pragma unroll
        for (int v = tid; v < BM * 4; v += 256) {
            int r = v >> 2, c4 = v & 3;
            int gr = rowBase + r;
            int sz = (gr < M) ? 16 : 0;
            size_t gi = (size_t)gr * K + c * 32 + c4 * 8;
            cp16(smem_u32(dAh + r * STR + c4 * 8), &Ah[gi], sz);
            cp16(smem_u32(dAl + r * STR + c4 * 8), &Al[gi], sz);
        }
#pragma unroll
        for (int v = tid; v < BN * 4; v += 256) {
            int r = v >> 2, c4 = v & 3;
            size_t gi = (size_t)(colBase + r) * K + c * 32 + c4 * 8;
            cp16(smem_u32(dBh + r * STR + c4 * 8), &Bh[gi], 16);
            cp16(smem_u32(dBl + r * STR + c4 * 8), &Bl[gi], 16);
        }
    };

    load_stage(0, 0);
    CP_COMMIT();

    for (int c = 0; c < chunks; c++) {
        if (c + 1 < chunks) {
            load_stage((c + 1) & 1, c + 1);
            CP_COMMIT();
            CP_WAIT(1);
        } else {
            CP_WAIT(0);
        }
        __syncthreads();

        const uint32_t stE = (uint32_t)((c & 1) * STAGE);
        const uint32_t aAddr = sbase + (stE + (uint32_t)(aRow * STR + aCol)) * 2;
        const uint32_t bAddr = sbase + (stE + (uint32_t)(bRow * STR + bCol)) * 2;

#pragma unroll
        for (int ks = 0; ks < 2; ks++) {
            uint32_t ah[2][4], al[2][4];
#pragma unroll
            for (int mf = 0; mf < 2; mf++) {
                uint32_t a = aAddr + (uint32_t)(mf * 16 * STR + ks * 16) * 2;
                ldsm_x4(ah[mf], a);
                ldsm_x4(al[mf], a + offAl * 2);
            }
#pragma unroll
            for (int nfp = 0; nfp < NF / 2; nfp++) {
                uint32_t bh[4], bl[4];
                uint32_t b = bAddr + (uint32_t)(nfp * 16 * STR + ks * 16) * 2;
                ldsm_x4(bh, b + offBh * 2);
                ldsm_x4(bl, b + offBl * 2);
#pragma unroll
                for (int j = 0; j < 2; j++) {
                    int nf = nfp * 2 + j;
#pragma unroll
                    for (int mf = 0; mf < 2; mf++) {
                        mma16816(acc[mf][nf], ah[mf], &bh[2 * j]);
                        mma16816(acc[mf][nf], ah[mf], &bl[2 * j]);
                        mma16816(acc[mf][nf], al[mf], &bh[2 * j]);
                    }
                }
            }
        }
        __syncthreads();
    }

    // epilogue: bias + act (+ bf16 split), straight from fragments
#pragma unroll
    for (int nf = 0; nf < NF; nf++) {
        int col = colBase + wC * WNT + nf * 8 + tid4 * 2;
        float b0 = bias[col], b1 = bias[col + 1];
#pragma unroll
        for (int mf = 0; mf < 2; mf++) {
#pragma unroll
            for (int half = 0; half < 2; half++) {
                int row = rowBase + wR * 32 + mf * 16 + gid + half * 8;
                if (row >= M) continue;
                float v0 = acc[mf][nf][half * 2] + b0;
                float v1 = acc[mf][nf][half * 2 + 1] + b1;
                if (ACT == 1) { v0 = fmaxf(v0, 0.f); v1 = fmaxf(v1, 0.f); }
                size_t oi = (size_t)row * Nn + col;
                if (WF32) *(float2*)&Cf[oi] = make_float2(v0, v1);
                if (WB16) {
                    __nv_bfloat162 hh2, ll2;
                    split_bf16(v0, hh2.x, ll2.x);
                    split_bf16(v1, hh2.y, ll2.y);
                    *(__nv_bfloat162*)&Ch[oi] = hh2;
                    *(__nv_bfloat162*)&Cl[oi] = ll2;
                }
            }
        }
    }
}

// ================= fused GATv2 layer (2-edge unrolled) =======================
// xlr: [NN][512], xl = cols 0..255, xr = cols 256..511
template <bool WB16>
__global__ __launch_bounds__(128)
void k_gat(const float* __restrict__ xlr,
           const float* __restrict__ att, const float* __restrict__ bias,
           float* __restrict__ out, __nv_bfloat16* outH, __nv_bfloat16* outL) {
    const int i = blockIdx.x;
    const int w = threadIdx.x >> 5;
    const int lane = threadIdx.x & 31;
    const int f = w * HID + lane * 2;
    const int s0 = g_off[i], s1 = g_off[i + 1];   // s1 > s0 (self loop)

    const float2 xrv = *(const float2*)(xlr + (size_t)i * 512 + 256 + f);
    const float2 atv = *(const float2*)(att + f);

    float acc0 = 0.f, acc1 = 0.f, den = 0.f;
    int p = s0;
    for (; p + 2 <= s1; p += 2) {
        int sA = __ldg(&g_src[p]);
        int sB = __ldg(&g_src[p + 1]);
        float2 xvA = *(const float2*)(xlr + (size_t)sA * 512 + f);
        float2 xvB = *(const float2*)(xlr + (size_t)sB * 512 + f);
        float a0 = xvA.x + xrv.x; a0 = a0 > 0.f ? a0 : 0.2f * a0;
        float a1 = xvA.y + xrv.y; a1 = a1 > 0.f ? a1 : 0.2f * a1;
        float b0 = xvB.x + xrv.x; b0 = b0 > 0.f ? b0 : 0.2f * b0;
        float b1 = xvB.y + xrv.y; b1 = b1 > 0.f ? b1 : 0.2f * b1;
        float sa = a0 * atv.x + a1 * atv.y;
        float sb = b0 * atv.x + b1 * atv.y;
#pragma unroll
        for (int o = 16; o; o >>= 1) {
            sa += __shfl_xor_sync(0xffffffffu, sa, o);
            sb += __shfl_xor_sync(0xffffffffu, sb, o);
        }
        float exa = __expf(sa), exb = __expf(sb);
        acc0 += exa * xvA.x + exb * xvB.x;
        acc1 += exa * xvA.y + exb * xvB.y;
        den  += exa + exb;
    }
    if (p < s1) {
        int sA = __ldg(&g_src[p]);
        float2 xvA = *(const float2*)(xlr + (size_t)sA * 512 + f);
        float a0 = xvA.x + xrv.x; a0 = a0 > 0.f ? a0 : 0.2f * a0;
        float a1 = xvA.y + xrv.y; a1 = a1 > 0.f ? a1 : 0.2f * a1;
        float sa = a0 * atv.x + a1 * atv.y;
#pragma unroll
        for (int o = 16; o; o >>= 1) sa += __shfl_xor_sync(0xffffffffu, sa, o);
        float exa = __expf(sa);
        acc0 += exa * xvA.x; acc1 += exa * xvA.y; den += exa;
    }
    float rr = 1.f / (den + 1e-16f);
    float o0 = fmaxf(acc0 * rr + bias[f], 0.f);
    float o1 = fmaxf(acc1 * rr + bias[f + 1], 0.f);
    size_t oi = (size_t)i * DD + f;
    out[oi] = o0; out[oi + 1] = o1;
    if (WB16) {
        __nv_bfloat162 h, l;
        split_bf16(o0, h.x, l.x); split_bf16(o1, h.y, l.y);
        *(__nv_bfloat162*)&outH[oi] = h;
        *(__nv_bfloat162*)&outL[oi] = l;
    }
}

// ================= dueling head (feat gather fused) ==========================
__global__ void k_head(const int* __restrict__ idx,
                       const float* __restrict__ h,
                       const float* __restrict__ h2,
                       const float* __restrict__ h3,
                       const float* __restrict__ qw1, const float* __restrict__ qb1,
                       const float* __restrict__ qw2, const float* __restrict__ qb2,
                       const float* __restrict__ vw1, const float* __restrict__ vb1,
                       const float* __restrict__ vw2, const float* __restrict__ vb2,
                       float* __restrict__ out) {
    __shared__ float f[CAT];
    __shared__ float r0[DUEL_H], r1[DUEL_H], r2[DUEL_H];
    int b = blockIdx.x, t = threadIdx.x;
    int n = idx[b];
    for (int i = t; i < CAT; i += DUEL_H) {
        float v;
        if (i < HID)            v = h[(size_t)n * HID + i];
        else if (i < HID + DD)  v = h2[(size_t)n * DD + (i - HID)];
        else                    v = h3[(size_t)n * DD + (i - HID - DD)];
        f[i] = v;
    }
    __syncthreads();
    float q = 0.f, v = 0.f;
#pragma unroll 4
    for (int k = 0; k < CAT; k++) {
        float fv = f[k];
        q += fv * qw1[(size_t)k * DUEL_H + t];
        v += fv * vw1[(size_t)k * DUEL_H + t];
    }
    q = fmaxf(q + qb1[t], 0.f);
    v = fmaxf(v + vb1[t], 0.f);
    r0[t] = q * qw2[t * 2 + 0];
    r1[t] = q * qw2[t * 2 + 1];
    r2[t] = v * vw2[t];
    __syncthreads();
    for (int o = 64; o; o >>= 1) {
        if (t < o) { r0[t] += r0[t + o]; r1[t] += r1[t + o]; r2[t] += r2[t + o]; }
        __syncthreads();
    }
    if (t == 0) {
        float q0 = r0[0] + qb2[0], q1 = r1[0] + qb2[1], vv = r2[0] + vb2[0];
        float m = 0.5f * (q0 + q1);
        out[b * 2 + 0] = q0 - m + vv;
        out[b * 2 + 1] = q1 - m + vv;
    }
}

// ================= launch ====================================================
extern "C" void kernel_launch(void* const* d_in, const int* in_sizes, int n_in,
                              void* d_out, int out_size) {
    const float* x      = (const float*)d_in[0];
    const int*   EI     = (const int*)  d_in[1];
    const int*   idx    = (const int*)  d_in[2];
    const float* enc_w1 = (const float*)d_in[3];
    const float* enc_b1 = (const float*)d_in[4];
    const float* enc_w2 = (const float*)d_in[5];
    const float* enc_b2 = (const float*)d_in[6];
    const float* wl1    = (const float*)d_in[7];
    const float* bl1    = (const float*)d_in[8];
    const float* wr1    = (const float*)d_in[9];
    const float* br1    = (const float*)d_in[10];
    const float* att1   = (const float*)d_in[11];
    const float* bias1  = (const float*)d_in[12];
    const float* wl2    = (const float*)d_in[13];
    const float* bl2    = (const float*)d_in[14];
    const float* wr2    = (const float*)d_in[15];
    const float* br2    = (const float*)d_in[16];
    const float* att2   = (const float*)d_in[17];
    const float* bias2  = (const float*)d_in[18];
    const float* q_w1   = (const float*)d_in[19];
    const float* q_b1   = (const float*)d_in[20];
    const float* q_w2   = (const float*)d_in[21];
    const float* q_b2   = (const float*)d_in[22];
    const float* v_w1   = (const float*)d_in[23];
    const float* v_b1   = (const float*)d_in[24];
    const float* v_w2   = (const float*)d_in[25];
    const float* v_b2   = (const float*)d_in[26];
    float* out = (float*)d_out;

    float *h, *xlr, *h2, *h3, *b1, *b2;
    __nv_bfloat16 *xh, *xlo, *h512h, *h512l, *hh, *hl, *h2h, *h2l, *wth, *wtl;
    cudaGetSymbolAddress((void**)&h,    g_h);
    cudaGetSymbolAddress((void**)&xlr,  g_xlr);
    cudaGetSymbolAddress((void**)&h2,   g_h2);
    cudaGetSymbolAddress((void**)&h3,   g_h3);
    cudaGetSymbolAddress((void**)&b1,   g_b1);
    cudaGetSymbolAddress((void**)&b2,   g_b2);
    cudaGetSymbolAddress((void**)&xh,   g_xh);
    cudaGetSymbolAddress((void**)&xlo,  g_xlo);
    cudaGetSymbolAddress((void**)&h512h, g_h512h);
    cudaGetSymbolAddress((void**)&h512l, g_h512l);
    cudaGetSymbolAddress((void**)&hh,   g_hh);
    cudaGetSymbolAddress((void**)&hl,   g_hl);
    cudaGetSymbolAddress((void**)&h2h,  g_h2h);
    cudaGetSymbolAddress((void**)&h2l,  g_h2l);
    cudaGetSymbolAddress((void**)&wth,  g_wth);
    cudaGetSymbolAddress((void**)&wtl,  g_wtl);

    const int SM_128_128 = 2 * (2 * 128 + 2 * 128) * STR * 2;   // 81,920 B
    const int SM_128_64  = 2 * (2 * 128 + 2 * 64) * STR * 2;    // 61,440 B
    cudaFuncSetAttribute((const void*)k_mma<128, 128, 1, 0, 1>, cudaFuncAttributeMaxDynamicSharedMemorySize, SM_128_128);
    cudaFuncSetAttribute((const void*)k_mma<128, 64, 1, 1, 1>,  cudaFuncAttributeMaxDynamicSharedMemorySize, SM_128_64);
    cudaFuncSetAttribute((const void*)k_mma<128, 128, 0, 1, 0>, cudaFuncAttributeMaxDynamicSharedMemorySize, SM_128_128);

    const int MT128 = (NN + 127) / 128;   // 157

    // prep
    k_split_x<<<(NN * HID + 255) / 256, 256>>>(x);
    k_wprep<<<896, 256>>>(enc_w1, enc_w2, wl1, wr1, wl2, wr2);
    k_bprep<<<4, 256>>>(bl1, br1, bl2, br2);

    // enc1: [NN,64] @ [64,512] -> h512 (bf16 hi/lo), relu
    k_mma<128, 128, 1, 0, 1><<<dim3(ENC_H / 128, MT128), 256, SM_128_128>>>(
        xh, xlo, wth + WOFF_ENC1, wtl + WOFF_ENC1, enc_b1, nullptr, h512h, h512l, NN, 64, ENC_H);
    k_count<<<(EP + 255) / 256, 256>>>(EI);
    // enc2: [NN,512] @ [512,64] -> h (f32 + bf16 hi/lo), relu
    k_mma<128, 64, 1, 1, 1><<<dim3(1, MT128), 256, SM_128_64>>>(
        h512h, h512l, wth + WOFF_ENC2, wtl + WOFF_ENC2, enc_b2, h, hh, hl, NN, ENC_H, HID);
    k_scan<<<1, 1024>>>();
    k_fill<<<(EP + 255) / 256, 256>>>(EI);

    // conv1: combined [xl|xr] transform, N=512
    k_mma<128, 128, 0, 1, 0><<<dim3(4, MT128), 256, SM_128_128>>>(
        hh, hl, wth + WOFF_W1, wtl + WOFF_W1, b1, xlr, nullptr, nullptr, NN, HID, 512);
    k_gat<true><<<NN, 128>>>(xlr, att1, bias1, h2, h2h, h2l);

    // conv2: combined transform, N=512, K=256
    k_mma<128, 128, 0, 1, 0><<<dim3(4, MT128), 256, SM_128_128>>>(
        h2h, h2l, wth + WOFF_W2, wtl + WOFF_W2, b2, xlr, nullptr, nullptr, NN, DD, 512);
    k_gat<false><<<NN, 128>>>(xlr, att2, bias2, h3, nullptr, nullptr);

    // heads (feat gather fused)
    k_head<<<BB, DUEL_H>>>(idx, h, h2, h3,
                           q_w1, q_b1, q_w2, q_b2, v_w1, v_b1, v_w2, v_b2, out);
}